// round 13
// baseline (speedup 1.0000x reference)
#include <cuda_runtime.h>
#include <cuda_fp16.h>
#include <math.h>
#include <stdint.h>

// Problem constants
#define C_DIM   256
#define N_TOK   4096
#define GROUPS  8
#define CPG     (C_DIM / GROUPS)        // 32
#define HEADS   8
#define HDIM    32
#define EPSV    1e-5f
#define GSIZE   (CPG * N_TOK)           // 131072 elems per group
#define SPLIT   4
#define KEYS_PER_SPLIT (N_TOK / SPLIT)  // 1024

// ---------------- scratch (static device globals; no allocation) -------------
__device__ float  g_part[64][2];              // groupnorm partial (sum, sumsq)
__device__ float  g_scale[C_DIM];             // per-channel gn scale
__device__ float  g_shift[C_DIM];             // per-channel gn shift
__device__ __half g_qh[HEADS * N_TOK * HDIM]; // Q fp16, token-major, pre-scaled (incl log2e)
__device__ __half g_kh[HEADS * N_TOK * HDIM]; // K fp16, token-major
__device__ __half g_vh[HEADS * HDIM * N_TOK]; // V fp16, dim-major
__device__ float  g_po[SPLIT * C_DIM * N_TOK]; // partial o, dim-major [split*256+c][n]
__device__ float  g_pl[SPLIT * HEADS * N_TOK]; // partial denom [(split*8+h)][n]

// ---------------- mma / ldmatrix / exp helpers --------------------------------
__device__ __forceinline__ void mma_f16(float* d,
                                        uint32_t a0, uint32_t a1, uint32_t a2, uint32_t a3,
                                        uint32_t b0, uint32_t b1) {
    asm volatile(
        "mma.sync.aligned.m16n8k16.row.col.f32.f16.f16.f32 "
        "{%0,%1,%2,%3}, {%4,%5,%6,%7}, {%8,%9}, {%0,%1,%2,%3};\n"
        : "+f"(d[0]), "+f"(d[1]), "+f"(d[2]), "+f"(d[3])
        : "r"(a0), "r"(a1), "r"(a2), "r"(a3), "r"(b0), "r"(b1));
}
__device__ __forceinline__ void mma_tf32(float* d, const uint32_t* a,
                                         uint32_t b0, uint32_t b1) {
    asm volatile(
        "mma.sync.aligned.m16n8k8.row.col.f32.tf32.tf32.f32 "
        "{%0,%1,%2,%3}, {%4,%5,%6,%7}, {%8,%9}, {%0,%1,%2,%3};\n"
        : "+f"(d[0]), "+f"(d[1]), "+f"(d[2]), "+f"(d[3])
        : "r"(a[0]), "r"(a[1]), "r"(a[2]), "r"(a[3]), "r"(b0), "r"(b1));
}
__device__ __forceinline__ void ldsm4(uint32_t& r0, uint32_t& r1, uint32_t& r2,
                                      uint32_t& r3, uint32_t addr) {
    asm volatile("ldmatrix.sync.aligned.m8n8.x4.shared.b16 {%0,%1,%2,%3}, [%4];"
                 : "=r"(r0), "=r"(r1), "=r"(r2), "=r"(r3) : "r"(addr));
}
__device__ __forceinline__ uint32_t smem_u32(const void* p) {
    return (uint32_t)__cvta_generic_to_shared(p);
}
// pack (lo,hi) to half2 then 2^x via one f16x2 MUFU op
__device__ __forceinline__ uint32_t h2exp2(float lo, float hi) {
    uint32_t h, r;
    asm("cvt.rn.f16x2.f32 %0, %1, %2;" : "=r"(h) : "f"(hi), "f"(lo));
    asm("ex2.approx.f16x2 %0, %1;" : "=r"(r) : "r"(h));
    return r;
}

// ---------------- GroupNorm: partial stats ------------------------------------
__global__ void gn_stats_kernel(const float* __restrict__ x, float* __restrict__ part) {
    int g  = blockIdx.x >> 3;
    int sl = blockIdx.x & 7;
    const float* xg = x + g * GSIZE + sl * (GSIZE / 8);
    float s = 0.f, ss = 0.f;
    for (int i = threadIdx.x; i < GSIZE / 8; i += 256) {
        float v = xg[i];
        s += v; ss += v * v;
    }
    for (int o = 16; o > 0; o >>= 1) {
        s  += __shfl_down_sync(0xffffffff, s,  o);
        ss += __shfl_down_sync(0xffffffff, ss, o);
    }
    __shared__ float rs[8], rss[8];
    int wid = threadIdx.x >> 5, lid = threadIdx.x & 31;
    if (lid == 0) { rs[wid] = s; rss[wid] = ss; }
    __syncthreads();
    if (threadIdx.x == 0) {
        float ts = 0.f, tss = 0.f;
        #pragma unroll
        for (int w = 0; w < 8; w++) { ts += rs[w]; tss += rss[w]; }
        part[blockIdx.x * 2 + 0] = ts;
        part[blockIdx.x * 2 + 1] = tss;
    }
}

// ---------------- GroupNorm: finalize per-channel scale/shift -----------------
__global__ void gn_final_kernel(const float* __restrict__ part,
                                const float* __restrict__ gamma,
                                const float* __restrict__ beta,
                                float* __restrict__ scl, float* __restrict__ shf) {
    int c = threadIdx.x;           // 256 threads
    int g = c >> 5;
    float s = 0.f, ss = 0.f;
    #pragma unroll
    for (int t = 0; t < 8; t++) {
        s  += part[(g * 8 + t) * 2 + 0];
        ss += part[(g * 8 + t) * 2 + 1];
    }
    float mean = s * (1.0f / GSIZE);
    float var  = ss * (1.0f / GSIZE) - mean * mean;
    float inv  = rsqrtf(var + EPSV);
    float ga   = gamma[c] * inv;
    scl[c] = ga;
    shf[c] = beta[c] - mean * ga;
}

// ---------------- tf32 tensor-core GEMM: Y = W[M,256] @ B[256,4096] -----------
// mode 0: B = x with inline GN affine; fp16 Q(scaled)/K/V outputs (smem repack)
// mode 1: B = combine(po over 4 splits) * invL; fp32 out + bias + residual
__global__ __launch_bounds__(128) void gemm16_kernel(
    const float* __restrict__ W, const float* __restrict__ Bsrc,
    const float* __restrict__ bias, const float* __restrict__ res,
    float* __restrict__ Yout,
    __half* __restrict__ qh, __half* __restrict__ kh, __half* __restrict__ vh,
    const float* __restrict__ scl, const float* __restrict__ shf,
    const float* __restrict__ pl,
    float qscale, int mode) {
    __shared__ __align__(16) float sA[64 * 20];
    __shared__ __align__(16) float sB[16 * 68];
    __shared__ float sSc[C_DIM], sSh[C_DIM];
    __shared__ __align__(16) float sInvL[HEADS * 64];
    __shared__ __align__(16) __half sH[64 * 72];

    const int tid  = threadIdx.x;
    const int warp = tid >> 5;
    const int lane = tid & 31;
    const int g    = lane >> 2;
    const int tg   = lane & 3;
    const int wrow = warp * 16;
    const int m0 = blockIdx.y * 64, n0 = blockIdx.x * 64;

    if (mode == 0) {
        #pragma unroll
        for (int i = tid; i < C_DIM; i += 128) { sSc[i] = scl[i]; sSh[i] = shf[i]; }
    } else {
        // per-(head, token) 1/L table for the fused combine
        #pragma unroll
        for (int i = tid; i < HEADS * 64; i += 128) {
            int h = i >> 6, nn = n0 + (i & 63);
            float L = pl[(0 * HEADS + h) * N_TOK + nn]
                    + pl[(1 * HEADS + h) * N_TOK + nn]
                    + pl[(2 * HEADS + h) * N_TOK + nn]
                    + pl[(3 * HEADS + h) * N_TOK + nn];
            sInvL[i] = 1.0f / L;
        }
    }
    __syncthreads();

    float acc[8][4];
    #pragma unroll
    for (int nt = 0; nt < 8; nt++)
        #pragma unroll
        for (int j = 0; j < 4; j++) acc[nt][j] = 0.f;

    for (int k0 = 0; k0 < C_DIM; k0 += 16) {
        #pragma unroll
        for (int it = 0; it < 2; it++) {
            int i = it * 128 + tid;
            int m = i >> 2, c = i & 3;
            float4 v = *(const float4*)&W[(m0 + m) * C_DIM + k0 + c * 4];
            *(float4*)&sA[m * 20 + c * 4] = v;
        }
        if (mode == 0) {
            #pragma unroll
            for (int it = 0; it < 2; it++) {
                int i = it * 128 + tid;
                int k = i >> 4, c = i & 15;
                float4 v = *(const float4*)&Bsrc[(k0 + k) * N_TOK + n0 + c * 4];
                float sc = sSc[k0 + k], sh = sSh[k0 + k];
                v.x = v.x * sc + sh; v.y = v.y * sc + sh;
                v.z = v.z * sc + sh; v.w = v.w * sc + sh;
                *(float4*)&sB[k * 68 + c * 4] = v;
            }
        } else {
            // fused split-combine: B[k][n] = (sum_s po_s[k][n]) * invL[head(k)][n]
            #pragma unroll
            for (int it = 0; it < 2; it++) {
                int i = it * 128 + tid;
                int k = i >> 4, c = i & 15;
                const float* p0 = &Bsrc[(size_t)(k0 + k) * N_TOK + n0 + c * 4];
                float4 v0 = *(const float4*)(p0);
                float4 v1 = *(const float4*)(p0 + (size_t)C_DIM * N_TOK);
                float4 v2 = *(const float4*)(p0 + (size_t)2 * C_DIM * N_TOK);
                float4 v3 = *(const float4*)(p0 + (size_t)3 * C_DIM * N_TOK);
                float4 il = *(const float4*)&sInvL[((k0 + k) >> 5) * 64 + c * 4];
                float4 v;
                v.x = (v0.x + v1.x + v2.x + v3.x) * il.x;
                v.y = (v0.y + v1.y + v2.y + v3.y) * il.y;
                v.z = (v0.z + v1.z + v2.z + v3.z) * il.z;
                v.w = (v0.w + v1.w + v2.w + v3.w) * il.w;
                *(float4*)&sB[k * 68 + c * 4] = v;
            }
        }
        __syncthreads();
        #pragma unroll
        for (int kc = 0; kc < 2; kc++) {
            int ko = kc * 8;
            uint32_t a[4];
            a[0] = __float_as_uint(sA[(wrow + g)     * 20 + ko + tg]);
            a[1] = __float_as_uint(sA[(wrow + g + 8) * 20 + ko + tg]);
            a[2] = __float_as_uint(sA[(wrow + g)     * 20 + ko + tg + 4]);
            a[3] = __float_as_uint(sA[(wrow + g + 8) * 20 + ko + tg + 4]);
            #pragma unroll
            for (int nt = 0; nt < 8; nt++) {
                uint32_t b0 = __float_as_uint(sB[(ko + tg)     * 68 + nt * 8 + g]);
                uint32_t b1 = __float_as_uint(sB[(ko + tg + 4) * 68 + nt * 8 + g]);
                mma_tf32(acc[nt], a, b0, b1);
            }
        }
        __syncthreads();
    }

    // ---- epilogue ----
    int mA = m0 + wrow + g, mB = mA + 8;
    float bv0 = bias[mA], bv1 = bias[mB];

    if (mode == 1) {
        #pragma unroll
        for (int nt = 0; nt < 8; nt++) {
            int n = n0 + nt * 8 + 2 * tg;
            Yout[mA * N_TOK + n]     = acc[nt][0] + bv0 + res[mA * N_TOK + n];
            Yout[mA * N_TOK + n + 1] = acc[nt][1] + bv0 + res[mA * N_TOK + n + 1];
            Yout[mB * N_TOK + n]     = acc[nt][2] + bv1 + res[mB * N_TOK + n];
            Yout[mB * N_TOK + n + 1] = acc[nt][3] + bv1 + res[mB * N_TOK + n + 1];
        }
        return;
    }

    // mode 0: fp16 QKV. Q rows (m<256) pre-scaled by qscale (scale*log2e).
    float q0s = (mA < C_DIM) ? qscale : 1.0f;
    float q1s = (mB < C_DIM) ? qscale : 1.0f;
    bool isV = (m0 >= 2 * C_DIM);
    int lmA = wrow + g, lmB = lmA + 8;
    #pragma unroll
    for (int nt = 0; nt < 8; nt++) {
        int ln = nt * 8 + 2 * tg;
        __half h00 = __float2half_rn((acc[nt][0] + bv0) * q0s);
        __half h01 = __float2half_rn((acc[nt][1] + bv0) * q0s);
        __half h10 = __float2half_rn((acc[nt][2] + bv1) * q1s);
        __half h11 = __float2half_rn((acc[nt][3] + bv1) * q1s);
        if (isV) {
            sH[lmA * 72 + ln] = h00; sH[lmA * 72 + ln + 1] = h01;
            sH[lmB * 72 + ln] = h10; sH[lmB * 72 + ln + 1] = h11;
        } else {
            sH[ln * 72 + lmA] = h00; sH[(ln + 1) * 72 + lmA] = h01;
            sH[ln * 72 + lmB] = h10; sH[(ln + 1) * 72 + lmB] = h11;
        }
    }
    __syncthreads();

    if (isV) {
        int chb = m0 - 2 * C_DIM;
        #pragma unroll
        for (int it = 0; it < 4; it++) {
            int i = it * 128 + tid;
            int chl = i >> 3, c = i & 7;
            uint4 v = *(const uint4*)&sH[chl * 72 + c * 8];
            *(uint4*)&vh[(chb + chl) * N_TOK + n0 + c * 8] = v;
        }
    } else {
        bool isQ = (m0 < C_DIM);
        __half* dst = isQ ? qh : kh;
        int mrel = isQ ? m0 : (m0 - C_DIM);
        #pragma unroll
        for (int it = 0; it < 4; it++) {
            int i = it * 128 + tid;
            int hl = i >> 8, t = (i >> 2) & 63, c = i & 3;
            uint4 v = *(const uint4*)&sH[t * 72 + hl * 32 + c * 8];
            int head = (mrel >> 5) + hl;
            *(uint4*)&dst[head * (N_TOK * HDIM) + (n0 + t) * HDIM + c * 8] = v;
        }
    }
}

// ---------------- Flash attention: fp16 m16n8k16, zero-shift, f16x2 exp -------
#define SKW 20    // sQ/sK row stride in 32-bit words (16 data + 4 pad)
#define SVW 36    // sV row stride in 32-bit words (32 data + 4 pad)
#define ONES2 0x3C003C00u   // half2(1.0, 1.0)
__global__ __launch_bounds__(128) void attn_kernel(const __half* __restrict__ qh,
                                                   const __half* __restrict__ kh,
                                                   const __half* __restrict__ vh,
                                                   float* __restrict__ po,
                                                   float* __restrict__ pl) {
    __shared__ __align__(16) uint32_t sQ2[64 * SKW];
    __shared__ __align__(16) uint32_t sK2[64 * SKW];
    __shared__ __align__(16) uint32_t sV2[HDIM * SVW];

    const int tid  = threadIdx.x;
    const int warp = tid >> 5;
    const int lane = tid & 31;
    const int g    = lane >> 2;
    const int tg   = lane & 3;
    const int head  = blockIdx.y;
    const int split = blockIdx.z;
    const int q0   = blockIdx.x * 64;
    const int wrow = warp * 16;

    const __half* Qp = qh + head * (N_TOK * HDIM);
    const __half* Kp = kh + head * (N_TOK * HDIM);
    const __half* Vp = vh + head * (HDIM * N_TOK);

    // ---- precompute ldmatrix lane base addresses (loop-invariant) ----
    const int mi = lane >> 3, r = lane & 7;
    uint32_t base_k[4], base_v[2];
    {
        uint32_t kbase = smem_u32(sK2);
        #pragma unroll
        for (int j = 0; j < 4; j++) {
            int key = (2 * j + (mi >> 1)) * 8 + r;
            base_k[j] = kbase + (key * SKW + (mi & 1) * 4) * 4;
        }
        uint32_t vbase = smem_u32(sV2);
        #pragma unroll
        for (int jj = 0; jj < 2; jj++) {
            int d = (2 * jj + (mi >> 1)) * 8 + r;
            base_v[jj] = vbase + (d * SVW + (mi & 1) * 4) * 4;
        }
    }

    #pragma unroll
    for (int it = 0; it < 2; it++) {
        int i = it * 128 + tid;
        int t = i >> 2, c = i & 3;
        uint4 v = *(const uint4*)&Qp[(q0 + t) * HDIM + c * 8];
        *(uint4*)&sQ2[t * SKW + c * 4] = v;
    }
    __syncthreads();

    uint32_t qa[2][4];
    #pragma unroll
    for (int ks = 0; ks < 2; ks++) {
        qa[ks][0] = sQ2[(wrow + g)     * SKW + ks * 8 + tg];
        qa[ks][1] = sQ2[(wrow + g + 8) * SKW + ks * 8 + tg];
        qa[ks][2] = sQ2[(wrow + g)     * SKW + ks * 8 + tg + 4];
        qa[ks][3] = sQ2[(wrow + g + 8) * SKW + ks * 8 + tg + 4];
    }

    float o[4][4];
    #pragma unroll
    for (int nt = 0; nt < 4; nt++)
        #pragma unroll
        for (int j = 0; j < 4; j++) o[nt][j] = 0.f;
    float lsum[4] = {0.f, 0.f, 0.f, 0.f};   // ones-MMA row-sum accumulator

    const int kbase0 = split * KEYS_PER_SPLIT;
    for (int k0 = kbase0; k0 < kbase0 + KEYS_PER_SPLIT; k0 += 64) {
        __syncthreads();
        #pragma unroll
        for (int it = 0; it < 2; it++) {
            int i = it * 128 + tid;
            int t = i >> 2, c = i & 3;
            uint4 v = *(const uint4*)&Kp[(k0 + t) * HDIM + c * 8];
            *(uint4*)&sK2[t * SKW + c * 4] = v;
        }
        #pragma unroll
        for (int it = 0; it < 2; it++) {
            int i = it * 128 + tid;
            int d = i >> 3, c = i & 7;
            uint4 v = *(const uint4*)&Vp[d * N_TOK + k0 + c * 8];
            *(uint4*)&sV2[d * SVW + c * 4] = v;
        }
        __syncthreads();

        // ---- phase 1: S[16 x 64] = Q . K^T ----
        float s[8][4];
        #pragma unroll
        for (int nt = 0; nt < 8; nt++)
            #pragma unroll
            for (int j = 0; j < 4; j++) s[nt][j] = 0.f;
        #pragma unroll
        for (int ks = 0; ks < 2; ks++) {
            #pragma unroll
            for (int j = 0; j < 4; j++) {
                uint32_t b00, b01, b10, b11;
                ldsm4(b00, b01, b10, b11, base_k[j] + ks * 32);
                mma_f16(s[2*j],   qa[ks][0], qa[ks][1], qa[ks][2], qa[ks][3], b00, b01);
                mma_f16(s[2*j+1], qa[ks][0], qa[ks][1], qa[ks][2], qa[ks][3], b10, b11);
            }
        }

        // ---- zero-shift exp via f16x2 MUFU, straight into A fragments ----
        uint32_t pa[4][4];
        #pragma unroll
        for (int nt = 0; nt < 8; nt++) {
            uint32_t lo = h2exp2(s[nt][0], s[nt][1]);
            uint32_t hi = h2exp2(s[nt][2], s[nt][3]);
            pa[nt >> 1][(nt & 1) * 2 + 0] = lo;
            pa[nt >> 1][(nt & 1) * 2 + 1] = hi;
        }

        // ---- phase 3: O += P.V  and  l += P.1 (ones-MMA row sum) ----
        #pragma unroll
        for (int ks = 0; ks < 4; ks++) {
            #pragma unroll
            for (int jj = 0; jj < 2; jj++) {
                uint32_t b00, b01, b10, b11;
                ldsm4(b00, b01, b10, b11, base_v[jj] + ks * 32);
                mma_f16(o[2*jj],   pa[ks][0], pa[ks][1], pa[ks][2], pa[ks][3], b00, b01);
                mma_f16(o[2*jj+1], pa[ks][0], pa[ks][1], pa[ks][2], pa[ks][3], b10, b11);
            }
            mma_f16(lsum, pa[ks][0], pa[ks][1], pa[ks][2], pa[ks][3], ONES2, ONES2);
        }
    }

    const int sidx = split * HEADS + head;
    int qA = q0 + wrow + g;
    int qB = qA + 8;
    if (tg == 0) {
        pl[sidx * N_TOK + qA] = lsum[0];
        pl[sidx * N_TOK + qB] = lsum[2];
    }
    // po dim-major: po[(split*256 + head*32 + d) * N_TOK + q]
    float* pob = po + ((size_t)split * C_DIM + head * HDIM) * N_TOK;
    #pragma unroll
    for (int nt = 0; nt < 4; nt++) {
        int d = nt * 8 + 2 * tg;
        pob[(d)     * N_TOK + qA] = o[nt][0];
        pob[(d + 1) * N_TOK + qA] = o[nt][1];
        pob[(d)     * N_TOK + qB] = o[nt][2];
        pob[(d + 1) * N_TOK + qB] = o[nt][3];
    }
}

// ---------------- launcher ----------------------------------------------------
extern "C" void kernel_launch(void* const* d_in, const int* in_sizes, int n_in,
                              void* d_out, int out_size) {
    const float* x      = (const float*)d_in[0];
    const float* gamma  = (const float*)d_in[1];
    const float* beta   = (const float*)d_in[2];
    const float* qkv_w  = (const float*)d_in[3];
    const float* qkv_b  = (const float*)d_in[4];
    const float* proj_w = (const float*)d_in[5];
    const float* proj_b = (const float*)d_in[6];
    float* out = (float*)d_out;

    float *p_part, *p_scale, *p_shift, *p_po, *p_pl;
    __half *p_qh, *p_kh, *p_vh;
    cudaGetSymbolAddress((void**)&p_part,  g_part);
    cudaGetSymbolAddress((void**)&p_scale, g_scale);
    cudaGetSymbolAddress((void**)&p_shift, g_shift);
    cudaGetSymbolAddress((void**)&p_qh,    g_qh);
    cudaGetSymbolAddress((void**)&p_kh,    g_kh);
    cudaGetSymbolAddress((void**)&p_vh,    g_vh);
    cudaGetSymbolAddress((void**)&p_po,    g_po);
    cudaGetSymbolAddress((void**)&p_pl,    g_pl);

    // 1/sqrt(32) * log2(e): scores come out in log2 domain
    const float qscale = 0.17677669529663687f * 1.44269504088896340f;

    // 1. GroupNorm stats + per-channel scale/shift
    gn_stats_kernel<<<64, 256>>>(x, p_part);
    gn_final_kernel<<<1, 256>>>(p_part, gamma, beta, p_scale, p_shift);

    // 2. QKV GEMM (tf32 MMA, fused GN affine, fp16 outputs)
    gemm16_kernel<<<dim3(N_TOK / 64, (3 * C_DIM) / 64), 128>>>(
        qkv_w, x, qkv_b, nullptr, nullptr,
        p_qh, p_kh, p_vh, p_scale, p_shift, nullptr, qscale, 0);

    // 3. Attention: fp16 flash kernel (zero-shift, f16x2 exp), split-KV x4
    attn_kernel<<<dim3(N_TOK / 64, HEADS, SPLIT), 128>>>(
        p_qh, p_kh, p_vh, p_po, p_pl);

    // 4. Proj GEMM with fused split-combine + bias + residual -> d_out
    gemm16_kernel<<<dim3(N_TOK / 64, C_DIM / 64), 128>>>(
        proj_w, p_po, proj_b, x, out,
        nullptr, nullptr, nullptr, p_scale, p_shift, p_pl, 1.0f, 1);
}

// round 14
// speedup vs baseline: 1.0334x; 1.0334x over previous
#include <cuda_runtime.h>
#include <cuda_fp16.h>
#include <math.h>
#include <stdint.h>

// Problem constants
#define C_DIM   256
#define N_TOK   4096
#define GROUPS  8
#define CPG     (C_DIM / GROUPS)        // 32
#define HEADS   8
#define HDIM    32
#define EPSV    1e-5f
#define GSIZE   (CPG * N_TOK)           // 131072 elems per group
#define SPLIT   4
#define KEYS_PER_SPLIT (N_TOK / SPLIT)  // 1024

// ---------------- scratch (static device globals; no allocation) -------------
__device__ float  g_part[64][2];              // groupnorm partial (sum, sumsq)
__device__ float  g_scale[C_DIM];             // per-channel gn scale
__device__ float  g_shift[C_DIM];             // per-channel gn shift
__device__ __half g_qh[HEADS * N_TOK * HDIM]; // Q fp16, token-major, pre-scaled (incl log2e)
__device__ __half g_kh[HEADS * N_TOK * HDIM]; // K fp16, token-major
__device__ __half g_vh[HEADS * HDIM * N_TOK]; // V fp16, dim-major
__device__ float  g_attn[C_DIM * N_TOK];      // combined attention output [C][N]
__device__ float  g_po[SPLIT * HEADS * N_TOK * HDIM]; // partial o [sidx][q][d]
__device__ float  g_pl[SPLIT * HEADS * N_TOK];        // partial denom

// ---------------- mma / ldmatrix / exp helpers --------------------------------
__device__ __forceinline__ void mma_f16(float* d,
                                        uint32_t a0, uint32_t a1, uint32_t a2, uint32_t a3,
                                        uint32_t b0, uint32_t b1) {
    asm volatile(
        "mma.sync.aligned.m16n8k16.row.col.f32.f16.f16.f32 "
        "{%0,%1,%2,%3}, {%4,%5,%6,%7}, {%8,%9}, {%0,%1,%2,%3};\n"
        : "+f"(d[0]), "+f"(d[1]), "+f"(d[2]), "+f"(d[3])
        : "r"(a0), "r"(a1), "r"(a2), "r"(a3), "r"(b0), "r"(b1));
}
__device__ __forceinline__ void mma_tf32(float* d, const uint32_t* a,
                                         uint32_t b0, uint32_t b1) {
    asm volatile(
        "mma.sync.aligned.m16n8k8.row.col.f32.tf32.tf32.f32 "
        "{%0,%1,%2,%3}, {%4,%5,%6,%7}, {%8,%9}, {%0,%1,%2,%3};\n"
        : "+f"(d[0]), "+f"(d[1]), "+f"(d[2]), "+f"(d[3])
        : "r"(a[0]), "r"(a[1]), "r"(a[2]), "r"(a[3]), "r"(b0), "r"(b1));
}
__device__ __forceinline__ void ldsm4(uint32_t& r0, uint32_t& r1, uint32_t& r2,
                                      uint32_t& r3, uint32_t addr) {
    asm volatile("ldmatrix.sync.aligned.m8n8.x4.shared.b16 {%0,%1,%2,%3}, [%4];"
                 : "=r"(r0), "=r"(r1), "=r"(r2), "=r"(r3) : "r"(addr));
}
__device__ __forceinline__ uint32_t smem_u32(const void* p) {
    return (uint32_t)__cvta_generic_to_shared(p);
}
// pack (lo,hi) to half2 then 2^x via one f16x2 MUFU op
__device__ __forceinline__ uint32_t h2exp2(float lo, float hi) {
    uint32_t h, r;
    asm("cvt.rn.f16x2.f32 %0, %1, %2;" : "=r"(h) : "f"(hi), "f"(lo));
    asm("ex2.approx.f16x2 %0, %1;" : "=r"(r) : "r"(h));
    return r;
}

// ---------------- GroupNorm: partial stats ------------------------------------
__global__ void gn_stats_kernel(const float* __restrict__ x, float* __restrict__ part) {
    int g  = blockIdx.x >> 3;
    int sl = blockIdx.x & 7;
    const float* xg = x + g * GSIZE + sl * (GSIZE / 8);
    float s = 0.f, ss = 0.f;
    for (int i = threadIdx.x; i < GSIZE / 8; i += 256) {
        float v = xg[i];
        s += v; ss += v * v;
    }
    for (int o = 16; o > 0; o >>= 1) {
        s  += __shfl_down_sync(0xffffffff, s,  o);
        ss += __shfl_down_sync(0xffffffff, ss, o);
    }
    __shared__ float rs[8], rss[8];
    int wid = threadIdx.x >> 5, lid = threadIdx.x & 31;
    if (lid == 0) { rs[wid] = s; rss[wid] = ss; }
    __syncthreads();
    if (threadIdx.x == 0) {
        float ts = 0.f, tss = 0.f;
        #pragma unroll
        for (int w = 0; w < 8; w++) { ts += rs[w]; tss += rss[w]; }
        part[blockIdx.x * 2 + 0] = ts;
        part[blockIdx.x * 2 + 1] = tss;
    }
}

// ---------------- GroupNorm: finalize per-channel scale/shift -----------------
__global__ void gn_final_kernel(const float* __restrict__ part,
                                const float* __restrict__ gamma,
                                const float* __restrict__ beta,
                                float* __restrict__ scl, float* __restrict__ shf) {
    int c = threadIdx.x;           // 256 threads
    int g = c >> 5;
    float s = 0.f, ss = 0.f;
    #pragma unroll
    for (int t = 0; t < 8; t++) {
        s  += part[(g * 8 + t) * 2 + 0];
        ss += part[(g * 8 + t) * 2 + 1];
    }
    float mean = s * (1.0f / GSIZE);
    float var  = ss * (1.0f / GSIZE) - mean * mean;
    float inv  = rsqrtf(var + EPSV);
    float ga   = gamma[c] * inv;
    scl[c] = ga;
    shf[c] = beta[c] - mean * ga;
}

// ---------------- tf32 tensor-core GEMM: Y = W[M,256] @ B[256,4096] -----------
// mode 0: B = x with inline GN affine; fp16 Q(scaled)/K/V outputs (smem repack)
// mode 1: B = attn out; fp32 out + bias + residual
__global__ __launch_bounds__(128) void gemm16_kernel(
    const float* __restrict__ W, const float* __restrict__ Bsrc,
    const float* __restrict__ bias, const float* __restrict__ res,
    float* __restrict__ Yout,
    __half* __restrict__ qh, __half* __restrict__ kh, __half* __restrict__ vh,
    const float* __restrict__ scl, const float* __restrict__ shf,
    float qscale, int mode) {
    __shared__ __align__(16) float sA[64 * 20];
    __shared__ __align__(16) float sB[16 * 68];
    __shared__ float sSc[C_DIM], sSh[C_DIM];
    __shared__ __align__(16) __half sH[64 * 72];

    const int tid  = threadIdx.x;
    const int warp = tid >> 5;
    const int lane = tid & 31;
    const int g    = lane >> 2;
    const int tg   = lane & 3;
    const int wrow = warp * 16;
    const int m0 = blockIdx.y * 64, n0 = blockIdx.x * 64;

    if (mode == 0) {
        #pragma unroll
        for (int i = tid; i < C_DIM; i += 128) { sSc[i] = scl[i]; sSh[i] = shf[i]; }
    }
    __syncthreads();

    float acc[8][4];
    #pragma unroll
    for (int nt = 0; nt < 8; nt++)
        #pragma unroll
        for (int j = 0; j < 4; j++) acc[nt][j] = 0.f;

    for (int k0 = 0; k0 < C_DIM; k0 += 16) {
        #pragma unroll
        for (int it = 0; it < 2; it++) {
            int i = it * 128 + tid;
            int m = i >> 2, c = i & 3;
            float4 v = *(const float4*)&W[(m0 + m) * C_DIM + k0 + c * 4];
            *(float4*)&sA[m * 20 + c * 4] = v;
        }
        #pragma unroll
        for (int it = 0; it < 2; it++) {
            int i = it * 128 + tid;
            int k = i >> 4, c = i & 15;
            float4 v = *(const float4*)&Bsrc[(k0 + k) * N_TOK + n0 + c * 4];
            if (mode == 0) {
                float sc = sSc[k0 + k], sh = sSh[k0 + k];
                v.x = v.x * sc + sh; v.y = v.y * sc + sh;
                v.z = v.z * sc + sh; v.w = v.w * sc + sh;
            }
            *(float4*)&sB[k * 68 + c * 4] = v;
        }
        __syncthreads();
        #pragma unroll
        for (int kc = 0; kc < 2; kc++) {
            int ko = kc * 8;
            uint32_t a[4];
            a[0] = __float_as_uint(sA[(wrow + g)     * 20 + ko + tg]);
            a[1] = __float_as_uint(sA[(wrow + g + 8) * 20 + ko + tg]);
            a[2] = __float_as_uint(sA[(wrow + g)     * 20 + ko + tg + 4]);
            a[3] = __float_as_uint(sA[(wrow + g + 8) * 20 + ko + tg + 4]);
            #pragma unroll
            for (int nt = 0; nt < 8; nt++) {
                uint32_t b0 = __float_as_uint(sB[(ko + tg)     * 68 + nt * 8 + g]);
                uint32_t b1 = __float_as_uint(sB[(ko + tg + 4) * 68 + nt * 8 + g]);
                mma_tf32(acc[nt], a, b0, b1);
            }
        }
        __syncthreads();
    }

    // ---- epilogue ----
    int mA = m0 + wrow + g, mB = mA + 8;
    float bv0 = bias[mA], bv1 = bias[mB];

    if (mode == 1) {
        #pragma unroll
        for (int nt = 0; nt < 8; nt++) {
            int n = n0 + nt * 8 + 2 * tg;
            Yout[mA * N_TOK + n]     = acc[nt][0] + bv0 + res[mA * N_TOK + n];
            Yout[mA * N_TOK + n + 1] = acc[nt][1] + bv0 + res[mA * N_TOK + n + 1];
            Yout[mB * N_TOK + n]     = acc[nt][2] + bv1 + res[mB * N_TOK + n];
            Yout[mB * N_TOK + n + 1] = acc[nt][3] + bv1 + res[mB * N_TOK + n + 1];
        }
        return;
    }

    // mode 0: fp16 QKV. Q rows (m<256) pre-scaled by qscale (scale*log2e).
    float q0s = (mA < C_DIM) ? qscale : 1.0f;
    float q1s = (mB < C_DIM) ? qscale : 1.0f;
    bool isV = (m0 >= 2 * C_DIM);
    int lmA = wrow + g, lmB = lmA + 8;
    #pragma unroll
    for (int nt = 0; nt < 8; nt++) {
        int ln = nt * 8 + 2 * tg;
        __half h00 = __float2half_rn((acc[nt][0] + bv0) * q0s);
        __half h01 = __float2half_rn((acc[nt][1] + bv0) * q0s);
        __half h10 = __float2half_rn((acc[nt][2] + bv1) * q1s);
        __half h11 = __float2half_rn((acc[nt][3] + bv1) * q1s);
        if (isV) {
            sH[lmA * 72 + ln] = h00; sH[lmA * 72 + ln + 1] = h01;
            sH[lmB * 72 + ln] = h10; sH[lmB * 72 + ln + 1] = h11;
        } else {
            sH[ln * 72 + lmA] = h00; sH[(ln + 1) * 72 + lmA] = h01;
            sH[ln * 72 + lmB] = h10; sH[(ln + 1) * 72 + lmB] = h11;
        }
    }
    __syncthreads();

    if (isV) {
        int chb = m0 - 2 * C_DIM;
        #pragma unroll
        for (int it = 0; it < 4; it++) {
            int i = it * 128 + tid;
            int chl = i >> 3, c = i & 7;
            uint4 v = *(const uint4*)&sH[chl * 72 + c * 8];
            *(uint4*)&vh[(chb + chl) * N_TOK + n0 + c * 8] = v;
        }
    } else {
        bool isQ = (m0 < C_DIM);
        __half* dst = isQ ? qh : kh;
        int mrel = isQ ? m0 : (m0 - C_DIM);
        #pragma unroll
        for (int it = 0; it < 4; it++) {
            int i = it * 128 + tid;
            int hl = i >> 8, t = (i >> 2) & 63, c = i & 3;
            uint4 v = *(const uint4*)&sH[t * 72 + hl * 32 + c * 8];
            int head = (mrel >> 5) + hl;
            *(uint4*)&dst[head * (N_TOK * HDIM) + (n0 + t) * HDIM + c * 8] = v;
        }
    }
}

// ---------------- Flash attention: fp16 m16n8k16, zero-shift, f16x2 exp -------
#define SKW 20    // sQ/sK row stride in 32-bit words (16 data + 4 pad)
#define SVW 36    // sV row stride in 32-bit words (32 data + 4 pad)
#define ONES2 0x3C003C00u   // half2(1.0, 1.0)
__global__ __launch_bounds__(128) void attn_kernel(const __half* __restrict__ qh,
                                                   const __half* __restrict__ kh,
                                                   const __half* __restrict__ vh,
                                                   float* __restrict__ po,
                                                   float* __restrict__ pl) {
    __shared__ __align__(16) uint32_t sQ2[64 * SKW];
    __shared__ __align__(16) uint32_t sK2[64 * SKW];
    __shared__ __align__(16) uint32_t sV2[HDIM * SVW];

    const int tid  = threadIdx.x;
    const int warp = tid >> 5;
    const int lane = tid & 31;
    const int g    = lane >> 2;
    const int tg   = lane & 3;
    const int head  = blockIdx.y;
    const int split = blockIdx.z;
    const int q0   = blockIdx.x * 64;
    const int wrow = warp * 16;

    const __half* Qp = qh + head * (N_TOK * HDIM);
    const __half* Kp = kh + head * (N_TOK * HDIM);
    const __half* Vp = vh + head * (HDIM * N_TOK);

    // ---- precompute ldmatrix lane base addresses (loop-invariant) ----
    const int mi = lane >> 3, r = lane & 7;
    uint32_t base_k[4], base_v[2];
    {
        uint32_t kbase = smem_u32(sK2);
        #pragma unroll
        for (int j = 0; j < 4; j++) {
            int key = (2 * j + (mi >> 1)) * 8 + r;
            base_k[j] = kbase + (key * SKW + (mi & 1) * 4) * 4;
        }
        uint32_t vbase = smem_u32(sV2);
        #pragma unroll
        for (int jj = 0; jj < 2; jj++) {
            int d = (2 * jj + (mi >> 1)) * 8 + r;
            base_v[jj] = vbase + (d * SVW + (mi & 1) * 4) * 4;
        }
    }

    #pragma unroll
    for (int it = 0; it < 2; it++) {
        int i = it * 128 + tid;
        int t = i >> 2, c = i & 3;
        uint4 v = *(const uint4*)&Qp[(q0 + t) * HDIM + c * 8];
        *(uint4*)&sQ2[t * SKW + c * 4] = v;
    }
    __syncthreads();

    uint32_t qa[2][4];
    #pragma unroll
    for (int ks = 0; ks < 2; ks++) {
        qa[ks][0] = sQ2[(wrow + g)     * SKW + ks * 8 + tg];
        qa[ks][1] = sQ2[(wrow + g + 8) * SKW + ks * 8 + tg];
        qa[ks][2] = sQ2[(wrow + g)     * SKW + ks * 8 + tg + 4];
        qa[ks][3] = sQ2[(wrow + g + 8) * SKW + ks * 8 + tg + 4];
    }

    float o[4][4];
    #pragma unroll
    for (int nt = 0; nt < 4; nt++)
        #pragma unroll
        for (int j = 0; j < 4; j++) o[nt][j] = 0.f;
    float lsum[4] = {0.f, 0.f, 0.f, 0.f};   // ones-MMA row-sum accumulator

    const int kbase0 = split * KEYS_PER_SPLIT;
    for (int k0 = kbase0; k0 < kbase0 + KEYS_PER_SPLIT; k0 += 64) {
        __syncthreads();
        #pragma unroll
        for (int it = 0; it < 2; it++) {
            int i = it * 128 + tid;
            int t = i >> 2, c = i & 3;
            uint4 v = *(const uint4*)&Kp[(k0 + t) * HDIM + c * 8];
            *(uint4*)&sK2[t * SKW + c * 4] = v;
        }
        #pragma unroll
        for (int it = 0; it < 2; it++) {
            int i = it * 128 + tid;
            int d = i >> 3, c = i & 7;
            uint4 v = *(const uint4*)&Vp[d * N_TOK + k0 + c * 8];
            *(uint4*)&sV2[d * SVW + c * 4] = v;
        }
        __syncthreads();

        // ---- phase 1: S[16 x 64] = Q . K^T ----
        float s[8][4];
        #pragma unroll
        for (int nt = 0; nt < 8; nt++)
            #pragma unroll
            for (int j = 0; j < 4; j++) s[nt][j] = 0.f;
        #pragma unroll
        for (int ks = 0; ks < 2; ks++) {
            #pragma unroll
            for (int j = 0; j < 4; j++) {
                uint32_t b00, b01, b10, b11;
                ldsm4(b00, b01, b10, b11, base_k[j] + ks * 32);
                mma_f16(s[2*j],   qa[ks][0], qa[ks][1], qa[ks][2], qa[ks][3], b00, b01);
                mma_f16(s[2*j+1], qa[ks][0], qa[ks][1], qa[ks][2], qa[ks][3], b10, b11);
            }
        }

        // ---- zero-shift exp via f16x2 MUFU, straight into A fragments ----
        uint32_t pa[4][4];
        #pragma unroll
        for (int nt = 0; nt < 8; nt++) {
            uint32_t lo = h2exp2(s[nt][0], s[nt][1]);
            uint32_t hi = h2exp2(s[nt][2], s[nt][3]);
            pa[nt >> 1][(nt & 1) * 2 + 0] = lo;
            pa[nt >> 1][(nt & 1) * 2 + 1] = hi;
        }

        // ---- phase 3: O += P.V  and  l += P.1 (ones-MMA row sum) ----
        #pragma unroll
        for (int ks = 0; ks < 4; ks++) {
            #pragma unroll
            for (int jj = 0; jj < 2; jj++) {
                uint32_t b00, b01, b10, b11;
                ldsm4(b00, b01, b10, b11, base_v[jj] + ks * 32);
                mma_f16(o[2*jj],   pa[ks][0], pa[ks][1], pa[ks][2], pa[ks][3], b00, b01);
                mma_f16(o[2*jj+1], pa[ks][0], pa[ks][1], pa[ks][2], pa[ks][3], b10, b11);
            }
            mma_f16(lsum, pa[ks][0], pa[ks][1], pa[ks][2], pa[ks][3], ONES2, ONES2);
        }
    }

    const int sidx = split * HEADS + head;
    int qA = q0 + wrow + g;
    int qB = qA + 8;
    if (tg == 0) {
        pl[sidx * N_TOK + qA] = lsum[0];
        pl[sidx * N_TOK + qB] = lsum[2];
    }
    // po token-major: po[(sidx*N_TOK + q)*HDIM + d] -- float2, full sectors
    float* pobA = po + ((size_t)sidx * N_TOK + qA) * HDIM;
    float* pobB = po + ((size_t)sidx * N_TOK + qB) * HDIM;
    #pragma unroll
    for (int nt = 0; nt < 4; nt++) {
        int d = nt * 8 + 2 * tg;
        *(float2*)&pobA[d] = make_float2(o[nt][0], o[nt][1]);
        *(float2*)&pobB[d] = make_float2(o[nt][2], o[nt][3]);
    }
}

// ---------------- combine split-KV partials (zero-shift: plain sums) ----------
__global__ void attn_combine_kernel(const float* __restrict__ po,
                                    const float* __restrict__ pl,
                                    float* __restrict__ outp) {
    int gid  = blockIdx.x * 256 + threadIdx.x;   // 0..32767
    int head = gid >> 12;
    int qi   = gid & (N_TOK - 1);

    float L = 0.f;
    #pragma unroll
    for (int i = 0; i < SPLIT; i++)
        L += pl[(i * HEADS + head) * N_TOK + qi];
    float inv = 1.f / L;

    float acc[HDIM];
    #pragma unroll
    for (int d = 0; d < HDIM; d++) acc[d] = 0.f;
    #pragma unroll
    for (int i = 0; i < SPLIT; i++) {
        const float* src = po + (((size_t)(i * HEADS + head)) * N_TOK + qi) * HDIM;
        #pragma unroll
        for (int d4 = 0; d4 < HDIM; d4 += 4) {
            float4 v = *(const float4*)&src[d4];
            acc[d4]     += v.x;
            acc[d4 + 1] += v.y;
            acc[d4 + 2] += v.z;
            acc[d4 + 3] += v.w;
        }
    }
    #pragma unroll
    for (int d = 0; d < HDIM; d++)
        outp[(head * HDIM + d) * N_TOK + qi] = acc[d] * inv;
}

// ---------------- launcher ----------------------------------------------------
extern "C" void kernel_launch(void* const* d_in, const int* in_sizes, int n_in,
                              void* d_out, int out_size) {
    const float* x      = (const float*)d_in[0];
    const float* gamma  = (const float*)d_in[1];
    const float* beta   = (const float*)d_in[2];
    const float* qkv_w  = (const float*)d_in[3];
    const float* qkv_b  = (const float*)d_in[4];
    const float* proj_w = (const float*)d_in[5];
    const float* proj_b = (const float*)d_in[6];
    float* out = (float*)d_out;

    float *p_part, *p_scale, *p_shift, *p_attn, *p_po, *p_pl;
    __half *p_qh, *p_kh, *p_vh;
    cudaGetSymbolAddress((void**)&p_part,  g_part);
    cudaGetSymbolAddress((void**)&p_scale, g_scale);
    cudaGetSymbolAddress((void**)&p_shift, g_shift);
    cudaGetSymbolAddress((void**)&p_qh,    g_qh);
    cudaGetSymbolAddress((void**)&p_kh,    g_kh);
    cudaGetSymbolAddress((void**)&p_vh,    g_vh);
    cudaGetSymbolAddress((void**)&p_attn,  g_attn);
    cudaGetSymbolAddress((void**)&p_po,    g_po);
    cudaGetSymbolAddress((void**)&p_pl,    g_pl);

    // 1/sqrt(32) * log2(e): scores come out in log2 domain
    const float qscale = 0.17677669529663687f * 1.44269504088896340f;

    // 1. GroupNorm stats + per-channel scale/shift
    gn_stats_kernel<<<64, 256>>>(x, p_part);
    gn_final_kernel<<<1, 256>>>(p_part, gamma, beta, p_scale, p_shift);

    // 2. QKV GEMM (tf32 MMA, fused GN affine, fp16 outputs)
    gemm16_kernel<<<dim3(N_TOK / 64, (3 * C_DIM) / 64), 128>>>(
        qkv_w, x, qkv_b, nullptr, nullptr,
        p_qh, p_kh, p_vh, p_scale, p_shift, qscale, 0);

    // 3. Attention: fp16 flash kernel (zero-shift, f16x2 exp), split-KV x4
    attn_kernel<<<dim3(N_TOK / 64, HEADS, SPLIT), 128>>>(
        p_qh, p_kh, p_vh, p_po, p_pl);
    attn_combine_kernel<<<(N_TOK * HEADS) / 256, 256>>>(p_po, p_pl, p_attn);

    // 4. Proj GEMM (tf32 MMA) + bias + residual -> d_out
    gemm16_kernel<<<dim3(N_TOK / 64, C_DIM / 64), 128>>>(
        proj_w, p_attn, proj_b, x, out,
        nullptr, nullptr, nullptr, p_scale, p_shift, 1.0f, 1);
}

// round 15
// speedup vs baseline: 1.0815x; 1.0465x over previous
#include <cuda_runtime.h>
#include <cuda_fp16.h>
#include <math.h>
#include <stdint.h>

// Problem constants
#define C_DIM   256
#define N_TOK   4096
#define GROUPS  8
#define CPG     (C_DIM / GROUPS)        // 32
#define HEADS   8
#define HDIM    32
#define EPSV    1e-5f
#define GSIZE   (CPG * N_TOK)           // 131072 elems per group
#define SPLIT   4
#define KEYS_PER_SPLIT (N_TOK / SPLIT)  // 1024
#define GN_SL   32                      // gn_stats slices per group

// ---------------- scratch (static device globals; no allocation) -------------
__device__ float  g_part[GROUPS * GN_SL][2];  // groupnorm partial (sum, sumsq)
__device__ float  g_scale[C_DIM];             // per-channel gn scale
__device__ float  g_shift[C_DIM];             // per-channel gn shift
__device__ __half g_qh[HEADS * N_TOK * HDIM]; // Q fp16, token-major, pre-scaled (incl log2e)
__device__ __half g_kh[HEADS * N_TOK * HDIM]; // K fp16, token-major
__device__ __half g_vh[HEADS * HDIM * N_TOK]; // V fp16, dim-major
__device__ float  g_attn[C_DIM * N_TOK];      // combined attention output [C][N]
__device__ float  g_po[SPLIT * HEADS * N_TOK * HDIM]; // partial o [sidx][q][d]
__device__ float  g_pl[SPLIT * HEADS * N_TOK];        // partial denom

// ---------------- mma / ldmatrix / exp helpers --------------------------------
__device__ __forceinline__ void mma_f16(float* d,
                                        uint32_t a0, uint32_t a1, uint32_t a2, uint32_t a3,
                                        uint32_t b0, uint32_t b1) {
    asm volatile(
        "mma.sync.aligned.m16n8k16.row.col.f32.f16.f16.f32 "
        "{%0,%1,%2,%3}, {%4,%5,%6,%7}, {%8,%9}, {%0,%1,%2,%3};\n"
        : "+f"(d[0]), "+f"(d[1]), "+f"(d[2]), "+f"(d[3])
        : "r"(a0), "r"(a1), "r"(a2), "r"(a3), "r"(b0), "r"(b1));
}
__device__ __forceinline__ void ldsm4(uint32_t& r0, uint32_t& r1, uint32_t& r2,
                                      uint32_t& r3, uint32_t addr) {
    asm volatile("ldmatrix.sync.aligned.m8n8.x4.shared.b16 {%0,%1,%2,%3}, [%4];"
                 : "=r"(r0), "=r"(r1), "=r"(r2), "=r"(r3) : "r"(addr));
}
__device__ __forceinline__ void ldsm4t(uint32_t& r0, uint32_t& r1, uint32_t& r2,
                                       uint32_t& r3, uint32_t addr) {
    asm volatile("ldmatrix.sync.aligned.m8n8.x4.trans.shared.b16 {%0,%1,%2,%3}, [%4];"
                 : "=r"(r0), "=r"(r1), "=r"(r2), "=r"(r3) : "r"(addr));
}
__device__ __forceinline__ uint32_t smem_u32(const void* p) {
    return (uint32_t)__cvta_generic_to_shared(p);
}
// pack (lo,hi) to half2 then 2^x via one f16x2 MUFU op
__device__ __forceinline__ uint32_t h2exp2(float lo, float hi) {
    uint32_t h, r;
    asm("cvt.rn.f16x2.f32 %0, %1, %2;" : "=r"(h) : "f"(hi), "f"(lo));
    asm("ex2.approx.f16x2 %0, %1;" : "=r"(r) : "r"(h));
    return r;
}
__device__ __forceinline__ uint32_t pkh2(float a, float b) {
    __half2 h = __floats2half2_rn(a, b);
    return *(uint32_t*)&h;
}

// ---------------- GroupNorm: partial stats (256 blocks) ------------------------
__global__ void gn_stats_kernel(const float* __restrict__ x, float* __restrict__ part) {
    int g  = blockIdx.x >> 5;
    int sl = blockIdx.x & 31;
    const float* xg = x + g * GSIZE + sl * (GSIZE / GN_SL);
    float s = 0.f, ss = 0.f;
    for (int i = threadIdx.x; i < GSIZE / GN_SL; i += 256) {
        float v = xg[i];
        s += v; ss += v * v;
    }
    for (int o = 16; o > 0; o >>= 1) {
        s  += __shfl_down_sync(0xffffffff, s,  o);
        ss += __shfl_down_sync(0xffffffff, ss, o);
    }
    __shared__ float rs[8], rss[8];
    int wid = threadIdx.x >> 5, lid = threadIdx.x & 31;
    if (lid == 0) { rs[wid] = s; rss[wid] = ss; }
    __syncthreads();
    if (threadIdx.x == 0) {
        float ts = 0.f, tss = 0.f;
        #pragma unroll
        for (int w = 0; w < 8; w++) { ts += rs[w]; tss += rss[w]; }
        part[blockIdx.x * 2 + 0] = ts;
        part[blockIdx.x * 2 + 1] = tss;
    }
}

// ---------------- GroupNorm: finalize per-channel scale/shift -----------------
__global__ void gn_final_kernel(const float* __restrict__ part,
                                const float* __restrict__ gamma,
                                const float* __restrict__ beta,
                                float* __restrict__ scl, float* __restrict__ shf) {
    int c = threadIdx.x;           // 256 threads
    int g = c >> 5;
    float s = 0.f, ss = 0.f;
    #pragma unroll
    for (int t = 0; t < GN_SL; t++) {
        s  += part[(g * GN_SL + t) * 2 + 0];
        ss += part[(g * GN_SL + t) * 2 + 1];
    }
    float mean = s * (1.0f / GSIZE);
    float var  = ss * (1.0f / GSIZE) - mean * mean;
    float inv  = rsqrtf(var + EPSV);
    float ga   = gamma[c] * inv;
    scl[c] = ga;
    shf[c] = beta[c] - mean * ga;
}

// ---------------- fp16 tensor-core GEMM: Y = W[M,256] @ B[256,4096] -----------
// A (W) fp16 row-major in smem (stride GAW words); B (H) fp16 k-major (stride
// GBW words), fragments via ldmatrix / ldmatrix.trans. BK=32.
// mode 0: B = x with inline GN affine; fp16 Q(scaled)/K/V outputs (smem repack)
// mode 1: B = attn out; fp32 out + bias + residual
#define GAW 20   // sA row stride: 16 data words (32 halves) + 4 pad
#define GBW 36   // sB row stride: 32 data words (64 halves) + 4 pad
__global__ __launch_bounds__(128) void gemm16_kernel(
    const float* __restrict__ W, const float* __restrict__ Bsrc,
    const float* __restrict__ bias, const float* __restrict__ res,
    float* __restrict__ Yout,
    __half* __restrict__ qh, __half* __restrict__ kh, __half* __restrict__ vh,
    const float* __restrict__ scl, const float* __restrict__ shf,
    float qscale, int mode) {
    __shared__ __align__(16) uint32_t sA[64 * GAW];
    __shared__ __align__(16) uint32_t sB[32 * GBW];
    __shared__ float sSc[C_DIM], sSh[C_DIM];
    __shared__ __align__(16) __half sH[64 * 72];

    const int tid  = threadIdx.x;
    const int warp = tid >> 5;
    const int lane = tid & 31;
    const int g    = lane >> 2;
    const int tg   = lane & 3;
    const int wrow = warp * 16;
    const int m0 = blockIdx.y * 64, n0 = blockIdx.x * 64;

    if (mode == 0) {
        #pragma unroll
        for (int i = tid; i < C_DIM; i += 128) { sSc[i] = scl[i]; sSh[i] = shf[i]; }
    }
    __syncthreads();

    // ldmatrix lane base addresses (loop-invariant)
    const int mi = lane >> 3, r = lane & 7;
    const uint32_t a_base = smem_u32(sA)
        + ((wrow + (mi & 1) * 8 + r) * GAW + (mi >> 1) * 4) * 4;
    const uint32_t b_base = smem_u32(sB)
        + (((mi & 1) * 8 + r) * GBW + (mi >> 1) * 4) * 4;

    float acc[8][4];
    #pragma unroll
    for (int nt = 0; nt < 8; nt++)
        #pragma unroll
        for (int j = 0; j < 4; j++) acc[nt][j] = 0.f;

    for (int k0 = 0; k0 < C_DIM; k0 += 32) {
        // ---- A tile: W[64m x 32k] fp32 -> fp16, STS.128 conflict-free ----
        {
            int m = tid & 63, hh = tid >> 6;   // hh 0..1
            #pragma unroll
            for (int j = 0; j < 2; j++) {
                int h = hh * 2 + j;            // 16B chunk (8 halves)
                const float* wp = &W[(m0 + m) * C_DIM + k0 + h * 8];
                float4 w0 = *(const float4*)wp;
                float4 w1 = *(const float4*)(wp + 4);
                uint4 pk;
                pk.x = pkh2(w0.x, w0.y); pk.y = pkh2(w0.z, w0.w);
                pk.z = pkh2(w1.x, w1.y); pk.w = pkh2(w1.z, w1.w);
                *(uint4*)&sA[m * GAW + h * 4] = pk;
            }
        }
        // ---- B tile: Bsrc[32k x 64n] fp32 -> fp16 (+affine mode0), STS.64 ----
        #pragma unroll
        for (int p = 0; p < 4; p++) {
            int idx = p * 128 + tid;
            int k = idx >> 4, n4 = idx & 15;   // n4*4 = n offset
            float4 v = *(const float4*)&Bsrc[(k0 + k) * N_TOK + n0 + n4 * 4];
            if (mode == 0) {
                float sc = sSc[k0 + k], sh = sSh[k0 + k];
                v.x = v.x * sc + sh; v.y = v.y * sc + sh;
                v.z = v.z * sc + sh; v.w = v.w * sc + sh;
            }
            uint2 pk;
            pk.x = pkh2(v.x, v.y); pk.y = pkh2(v.z, v.w);
            *(uint2*)&sB[k * GBW + n4 * 2] = pk;
        }
        __syncthreads();

        // ---- fragments + MMA: 2 k-chunks of 16, 8 n-octets ----
        #pragma unroll
        for (int kc = 0; kc < 2; kc++) {
            uint32_t a0, a1, a2, a3;
            ldsm4(a0, a1, a2, a3, a_base + kc * 32);
            uint32_t bk = b_base + kc * 16 * GBW * 4;
            #pragma unroll
            for (int ns = 0; ns < 4; ns++) {
                uint32_t b00, b01, b10, b11;
                ldsm4t(b00, b01, b10, b11, bk + ns * 32);
                mma_f16(acc[2 * ns],     a0, a1, a2, a3, b00, b01);
                mma_f16(acc[2 * ns + 1], a0, a1, a2, a3, b10, b11);
            }
        }
        __syncthreads();
    }

    // ---- epilogue ----
    int mA = m0 + wrow + g, mB = mA + 8;
    float bv0 = bias[mA], bv1 = bias[mB];

    if (mode == 1) {
        #pragma unroll
        for (int nt = 0; nt < 8; nt++) {
            int n = n0 + nt * 8 + 2 * tg;
            Yout[mA * N_TOK + n]     = acc[nt][0] + bv0 + res[mA * N_TOK + n];
            Yout[mA * N_TOK + n + 1] = acc[nt][1] + bv0 + res[mA * N_TOK + n + 1];
            Yout[mB * N_TOK + n]     = acc[nt][2] + bv1 + res[mB * N_TOK + n];
            Yout[mB * N_TOK + n + 1] = acc[nt][3] + bv1 + res[mB * N_TOK + n + 1];
        }
        return;
    }

    // mode 0: fp16 QKV. Q rows (m<256) pre-scaled by qscale (scale*log2e).
    float q0s = (mA < C_DIM) ? qscale : 1.0f;
    float q1s = (mB < C_DIM) ? qscale : 1.0f;
    bool isV = (m0 >= 2 * C_DIM);
    int lmA = wrow + g, lmB = lmA + 8;
    #pragma unroll
    for (int nt = 0; nt < 8; nt++) {
        int ln = nt * 8 + 2 * tg;
        __half h00 = __float2half_rn((acc[nt][0] + bv0) * q0s);
        __half h01 = __float2half_rn((acc[nt][1] + bv0) * q0s);
        __half h10 = __float2half_rn((acc[nt][2] + bv1) * q1s);
        __half h11 = __float2half_rn((acc[nt][3] + bv1) * q1s);
        if (isV) {
            sH[lmA * 72 + ln] = h00; sH[lmA * 72 + ln + 1] = h01;
            sH[lmB * 72 + ln] = h10; sH[lmB * 72 + ln + 1] = h11;
        } else {
            sH[ln * 72 + lmA] = h00; sH[(ln + 1) * 72 + lmA] = h01;
            sH[ln * 72 + lmB] = h10; sH[(ln + 1) * 72 + lmB] = h11;
        }
    }
    __syncthreads();

    if (isV) {
        int chb = m0 - 2 * C_DIM;
        #pragma unroll
        for (int it = 0; it < 4; it++) {
            int i = it * 128 + tid;
            int chl = i >> 3, c = i & 7;
            uint4 v = *(const uint4*)&sH[chl * 72 + c * 8];
            *(uint4*)&vh[(chb + chl) * N_TOK + n0 + c * 8] = v;
        }
    } else {
        bool isQ = (m0 < C_DIM);
        __half* dst = isQ ? qh : kh;
        int mrel = isQ ? m0 : (m0 - C_DIM);
        #pragma unroll
        for (int it = 0; it < 4; it++) {
            int i = it * 128 + tid;
            int hl = i >> 8, t = (i >> 2) & 63, c = i & 3;
            uint4 v = *(const uint4*)&sH[t * 72 + hl * 32 + c * 8];
            int head = (mrel >> 5) + hl;
            *(uint4*)&dst[head * (N_TOK * HDIM) + (n0 + t) * HDIM + c * 8] = v;
        }
    }
}

// ---------------- Flash attention: fp16 m16n8k16, zero-shift, f16x2 exp -------
#define SKW 20    // sQ/sK row stride in 32-bit words (16 data + 4 pad)
#define SVW 36    // sV row stride in 32-bit words (32 data + 4 pad)
#define ONES2 0x3C003C00u   // half2(1.0, 1.0)
__global__ __launch_bounds__(128) void attn_kernel(const __half* __restrict__ qh,
                                                   const __half* __restrict__ kh,
                                                   const __half* __restrict__ vh,
                                                   float* __restrict__ po,
                                                   float* __restrict__ pl) {
    __shared__ __align__(16) uint32_t sQ2[64 * SKW];
    __shared__ __align__(16) uint32_t sK2[64 * SKW];
    __shared__ __align__(16) uint32_t sV2[HDIM * SVW];

    const int tid  = threadIdx.x;
    const int warp = tid >> 5;
    const int lane = tid & 31;
    const int g    = lane >> 2;
    const int tg   = lane & 3;
    const int head  = blockIdx.y;
    const int split = blockIdx.z;
    const int q0   = blockIdx.x * 64;
    const int wrow = warp * 16;

    const __half* Qp = qh + head * (N_TOK * HDIM);
    const __half* Kp = kh + head * (N_TOK * HDIM);
    const __half* Vp = vh + head * (HDIM * N_TOK);

    // ---- precompute ldmatrix lane base addresses (loop-invariant) ----
    const int mi = lane >> 3, r = lane & 7;
    uint32_t base_k[4], base_v[2];
    {
        uint32_t kbase = smem_u32(sK2);
        #pragma unroll
        for (int j = 0; j < 4; j++) {
            int key = (2 * j + (mi >> 1)) * 8 + r;
            base_k[j] = kbase + (key * SKW + (mi & 1) * 4) * 4;
        }
        uint32_t vbase = smem_u32(sV2);
        #pragma unroll
        for (int jj = 0; jj < 2; jj++) {
            int d = (2 * jj + (mi >> 1)) * 8 + r;
            base_v[jj] = vbase + (d * SVW + (mi & 1) * 4) * 4;
        }
    }

    #pragma unroll
    for (int it = 0; it < 2; it++) {
        int i = it * 128 + tid;
        int t = i >> 2, c = i & 3;
        uint4 v = *(const uint4*)&Qp[(q0 + t) * HDIM + c * 8];
        *(uint4*)&sQ2[t * SKW + c * 4] = v;
    }
    __syncthreads();

    uint32_t qa[2][4];
    #pragma unroll
    for (int ks = 0; ks < 2; ks++) {
        qa[ks][0] = sQ2[(wrow + g)     * SKW + ks * 8 + tg];
        qa[ks][1] = sQ2[(wrow + g + 8) * SKW + ks * 8 + tg];
        qa[ks][2] = sQ2[(wrow + g)     * SKW + ks * 8 + tg + 4];
        qa[ks][3] = sQ2[(wrow + g + 8) * SKW + ks * 8 + tg + 4];
    }

    float o[4][4];
    #pragma unroll
    for (int nt = 0; nt < 4; nt++)
        #pragma unroll
        for (int j = 0; j < 4; j++) o[nt][j] = 0.f;
    float lsum[4] = {0.f, 0.f, 0.f, 0.f};   // ones-MMA row-sum accumulator

    const int kbase0 = split * KEYS_PER_SPLIT;
    for (int k0 = kbase0; k0 < kbase0 + KEYS_PER_SPLIT; k0 += 64) {
        __syncthreads();
        #pragma unroll
        for (int it = 0; it < 2; it++) {
            int i = it * 128 + tid;
            int t = i >> 2, c = i & 3;
            uint4 v = *(const uint4*)&Kp[(k0 + t) * HDIM + c * 8];
            *(uint4*)&sK2[t * SKW + c * 4] = v;
        }
        #pragma unroll
        for (int it = 0; it < 2; it++) {
            int i = it * 128 + tid;
            int d = i >> 3, c = i & 7;
            uint4 v = *(const uint4*)&Vp[d * N_TOK + k0 + c * 8];
            *(uint4*)&sV2[d * SVW + c * 4] = v;
        }
        __syncthreads();

        // ---- phase 1: S[16 x 64] = Q . K^T ----
        float s[8][4];
        #pragma unroll
        for (int nt = 0; nt < 8; nt++)
            #pragma unroll
            for (int j = 0; j < 4; j++) s[nt][j] = 0.f;
        #pragma unroll
        for (int ks = 0; ks < 2; ks++) {
            #pragma unroll
            for (int j = 0; j < 4; j++) {
                uint32_t b00, b01, b10, b11;
                ldsm4(b00, b01, b10, b11, base_k[j] + ks * 32);
                mma_f16(s[2*j],   qa[ks][0], qa[ks][1], qa[ks][2], qa[ks][3], b00, b01);
                mma_f16(s[2*j+1], qa[ks][0], qa[ks][1], qa[ks][2], qa[ks][3], b10, b11);
            }
        }

        // ---- zero-shift exp via f16x2 MUFU, straight into A fragments ----
        uint32_t pa[4][4];
        #pragma unroll
        for (int nt = 0; nt < 8; nt++) {
            uint32_t lo = h2exp2(s[nt][0], s[nt][1]);
            uint32_t hi = h2exp2(s[nt][2], s[nt][3]);
            pa[nt >> 1][(nt & 1) * 2 + 0] = lo;
            pa[nt >> 1][(nt & 1) * 2 + 1] = hi;
        }

        // ---- phase 3: O += P.V  and  l += P.1 (ones-MMA row sum) ----
        #pragma unroll
        for (int ks = 0; ks < 4; ks++) {
            #pragma unroll
            for (int jj = 0; jj < 2; jj++) {
                uint32_t b00, b01, b10, b11;
                ldsm4(b00, b01, b10, b11, base_v[jj] + ks * 32);
                mma_f16(o[2*jj],   pa[ks][0], pa[ks][1], pa[ks][2], pa[ks][3], b00, b01);
                mma_f16(o[2*jj+1], pa[ks][0], pa[ks][1], pa[ks][2], pa[ks][3], b10, b11);
            }
            mma_f16(lsum, pa[ks][0], pa[ks][1], pa[ks][2], pa[ks][3], ONES2, ONES2);
        }
    }

    const int sidx = split * HEADS + head;
    int qA = q0 + wrow + g;
    int qB = qA + 8;
    if (tg == 0) {
        pl[sidx * N_TOK + qA] = lsum[0];
        pl[sidx * N_TOK + qB] = lsum[2];
    }
    // po token-major: po[(sidx*N_TOK + q)*HDIM + d] -- float2, full sectors
    float* pobA = po + ((size_t)sidx * N_TOK + qA) * HDIM;
    float* pobB = po + ((size_t)sidx * N_TOK + qB) * HDIM;
    #pragma unroll
    for (int nt = 0; nt < 4; nt++) {
        int d = nt * 8 + 2 * tg;
        *(float2*)&pobA[d] = make_float2(o[nt][0], o[nt][1]);
        *(float2*)&pobB[d] = make_float2(o[nt][2], o[nt][3]);
    }
}

// ---------------- combine split-KV partials (zero-shift: plain sums) ----------
__global__ void attn_combine_kernel(const float* __restrict__ po,
                                    const float* __restrict__ pl,
                                    float* __restrict__ outp) {
    int gid  = blockIdx.x * 256 + threadIdx.x;   // 0..32767
    int head = gid >> 12;
    int qi   = gid & (N_TOK - 1);

    float L = 0.f;
    #pragma unroll
    for (int i = 0; i < SPLIT; i++)
        L += pl[(i * HEADS + head) * N_TOK + qi];
    float inv = 1.f / L;

    float acc[HDIM];
    #pragma unroll
    for (int d = 0; d < HDIM; d++) acc[d] = 0.f;
    #pragma unroll
    for (int i = 0; i < SPLIT; i++) {
        const float* src = po + (((size_t)(i * HEADS + head)) * N_TOK + qi) * HDIM;
        #pragma unroll
        for (int d4 = 0; d4 < HDIM; d4 += 4) {
            float4 v = *(const float4*)&src[d4];
            acc[d4]     += v.x;
            acc[d4 + 1] += v.y;
            acc[d4 + 2] += v.z;
            acc[d4 + 3] += v.w;
        }
    }
    #pragma unroll
    for (int d = 0; d < HDIM; d++)
        outp[(head * HDIM + d) * N_TOK + qi] = acc[d] * inv;
}

// ---------------- launcher ----------------------------------------------------
extern "C" void kernel_launch(void* const* d_in, const int* in_sizes, int n_in,
                              void* d_out, int out_size) {
    const float* x      = (const float*)d_in[0];
    const float* gamma  = (const float*)d_in[1];
    const float* beta   = (const float*)d_in[2];
    const float* qkv_w  = (const float*)d_in[3];
    const float* qkv_b  = (const float*)d_in[4];
    const float* proj_w = (const float*)d_in[5];
    const float* proj_b = (const float*)d_in[6];
    float* out = (float*)d_out;

    float *p_part, *p_scale, *p_shift, *p_attn, *p_po, *p_pl;
    __half *p_qh, *p_kh, *p_vh;
    cudaGetSymbolAddress((void**)&p_part,  g_part);
    cudaGetSymbolAddress((void**)&p_scale, g_scale);
    cudaGetSymbolAddress((void**)&p_shift, g_shift);
    cudaGetSymbolAddress((void**)&p_qh,    g_qh);
    cudaGetSymbolAddress((void**)&p_kh,    g_kh);
    cudaGetSymbolAddress((void**)&p_vh,    g_vh);
    cudaGetSymbolAddress((void**)&p_attn,  g_attn);
    cudaGetSymbolAddress((void**)&p_po,    g_po);
    cudaGetSymbolAddress((void**)&p_pl,    g_pl);

    // 1/sqrt(32) * log2(e): scores come out in log2 domain
    const float qscale = 0.17677669529663687f * 1.44269504088896340f;

    // 1. GroupNorm stats + per-channel scale/shift
    gn_stats_kernel<<<GROUPS * GN_SL, 256>>>(x, p_part);
    gn_final_kernel<<<1, 256>>>(p_part, gamma, beta, p_scale, p_shift);

    // 2. QKV GEMM (fp16 MMA + ldmatrix, fused GN affine, fp16 outputs)
    gemm16_kernel<<<dim3(N_TOK / 64, (3 * C_DIM) / 64), 128>>>(
        qkv_w, x, qkv_b, nullptr, nullptr,
        p_qh, p_kh, p_vh, p_scale, p_shift, qscale, 0);

    // 3. Attention: fp16 flash kernel (zero-shift, f16x2 exp), split-KV x4
    attn_kernel<<<dim3(N_TOK / 64, HEADS, SPLIT), 128>>>(
        p_qh, p_kh, p_vh, p_po, p_pl);
    attn_combine_kernel<<<(N_TOK * HEADS) / 256, 256>>>(p_po, p_pl, p_attn);

    // 4. Proj GEMM (fp16 MMA) + bias + residual -> d_out
    gemm16_kernel<<<dim3(N_TOK / 64, C_DIM / 64), 128>>>(
        proj_w, p_attn, proj_b, x, out,
        nullptr, nullptr, nullptr, p_scale, p_shift, 1.0f, 1);
}

// round 16
// speedup vs baseline: 1.1581x; 1.0708x over previous
#include <cuda_runtime.h>
#include <cuda_fp16.h>
#include <math.h>
#include <stdint.h>

// Problem constants
#define C_DIM   256
#define N_TOK   4096
#define GROUPS  8
#define CPG     (C_DIM / GROUPS)        // 32
#define HEADS   8
#define HDIM    32
#define EPSV    1e-5f
#define GSIZE   (CPG * N_TOK)           // 131072 elems per group
#define SPLIT   4
#define KEYS_PER_SPLIT (N_TOK / SPLIT)  // 1024
#define GN_SL   32                      // gn_stats slices per group

// ---------------- scratch (static device globals; no allocation) -------------
__device__ float  g_part[GROUPS * GN_SL][2];  // groupnorm partial (sum, sumsq)
__device__ float  g_scale[C_DIM];             // per-channel gn scale
__device__ float  g_shift[C_DIM];             // per-channel gn shift
__device__ __half g_qh[HEADS * N_TOK * HDIM]; // Q fp16, token-major, pre-scaled (incl log2e)
__device__ __half g_kh[HEADS * N_TOK * HDIM]; // K fp16, token-major
__device__ __half g_vh[HEADS * HDIM * N_TOK]; // V fp16, dim-major
__device__ float  g_attn[C_DIM * N_TOK];      // combined attention output [C][N]
__device__ float  g_po[SPLIT * HEADS * N_TOK * HDIM]; // partial o [sidx][q][d]
__device__ float  g_pl[SPLIT * HEADS * N_TOK];        // partial denom

// ---------------- mma / ldmatrix / cp.async / exp helpers ---------------------
__device__ __forceinline__ void mma_f16(float* d,
                                        uint32_t a0, uint32_t a1, uint32_t a2, uint32_t a3,
                                        uint32_t b0, uint32_t b1) {
    asm volatile(
        "mma.sync.aligned.m16n8k16.row.col.f32.f16.f16.f32 "
        "{%0,%1,%2,%3}, {%4,%5,%6,%7}, {%8,%9}, {%0,%1,%2,%3};\n"
        : "+f"(d[0]), "+f"(d[1]), "+f"(d[2]), "+f"(d[3])
        : "r"(a0), "r"(a1), "r"(a2), "r"(a3), "r"(b0), "r"(b1));
}
__device__ __forceinline__ void ldsm4(uint32_t& r0, uint32_t& r1, uint32_t& r2,
                                      uint32_t& r3, uint32_t addr) {
    asm volatile("ldmatrix.sync.aligned.m8n8.x4.shared.b16 {%0,%1,%2,%3}, [%4];"
                 : "=r"(r0), "=r"(r1), "=r"(r2), "=r"(r3) : "r"(addr));
}
__device__ __forceinline__ void ldsm4t(uint32_t& r0, uint32_t& r1, uint32_t& r2,
                                       uint32_t& r3, uint32_t addr) {
    asm volatile("ldmatrix.sync.aligned.m8n8.x4.trans.shared.b16 {%0,%1,%2,%3}, [%4];"
                 : "=r"(r0), "=r"(r1), "=r"(r2), "=r"(r3) : "r"(addr));
}
__device__ __forceinline__ uint32_t smem_u32(const void* p) {
    return (uint32_t)__cvta_generic_to_shared(p);
}
__device__ __forceinline__ void cp16(uint32_t dst, const void* src) {
    asm volatile("cp.async.cg.shared.global [%0], [%1], 16;" :: "r"(dst), "l"(src));
}
__device__ __forceinline__ void cp_commit() {
    asm volatile("cp.async.commit_group;");
}
template <int N> __device__ __forceinline__ void cp_wait() {
    asm volatile("cp.async.wait_group %0;" :: "n"(N));
}
// pack (lo,hi) to half2 then 2^x via one f16x2 MUFU op
__device__ __forceinline__ uint32_t h2exp2(float lo, float hi) {
    uint32_t h, r;
    asm("cvt.rn.f16x2.f32 %0, %1, %2;" : "=r"(h) : "f"(hi), "f"(lo));
    asm("ex2.approx.f16x2 %0, %1;" : "=r"(r) : "r"(h));
    return r;
}
__device__ __forceinline__ uint32_t pkh2(float a, float b) {
    __half2 h = __floats2half2_rn(a, b);
    return *(uint32_t*)&h;
}

// ---------------- GroupNorm: partial stats (256 blocks) ------------------------
__global__ void gn_stats_kernel(const float* __restrict__ x, float* __restrict__ part) {
    int g  = blockIdx.x >> 5;
    int sl = blockIdx.x & 31;
    const float* xg = x + g * GSIZE + sl * (GSIZE / GN_SL);
    float s = 0.f, ss = 0.f;
    for (int i = threadIdx.x; i < GSIZE / GN_SL; i += 256) {
        float v = xg[i];
        s += v; ss += v * v;
    }
    for (int o = 16; o > 0; o >>= 1) {
        s  += __shfl_down_sync(0xffffffff, s,  o);
        ss += __shfl_down_sync(0xffffffff, ss, o);
    }
    __shared__ float rs[8], rss[8];
    int wid = threadIdx.x >> 5, lid = threadIdx.x & 31;
    if (lid == 0) { rs[wid] = s; rss[wid] = ss; }
    __syncthreads();
    if (threadIdx.x == 0) {
        float ts = 0.f, tss = 0.f;
        #pragma unroll
        for (int w = 0; w < 8; w++) { ts += rs[w]; tss += rss[w]; }
        part[blockIdx.x * 2 + 0] = ts;
        part[blockIdx.x * 2 + 1] = tss;
    }
}

// ---------------- GroupNorm: finalize per-channel scale/shift -----------------
__global__ void gn_final_kernel(const float* __restrict__ part,
                                const float* __restrict__ gamma,
                                const float* __restrict__ beta,
                                float* __restrict__ scl, float* __restrict__ shf) {
    int c = threadIdx.x;           // 256 threads
    int g = c >> 5;
    float s = 0.f, ss = 0.f;
    #pragma unroll
    for (int t = 0; t < GN_SL; t++) {
        s  += part[(g * GN_SL + t) * 2 + 0];
        ss += part[(g * GN_SL + t) * 2 + 1];
    }
    float mean = s * (1.0f / GSIZE);
    float var  = ss * (1.0f / GSIZE) - mean * mean;
    float inv  = rsqrtf(var + EPSV);
    float ga   = gamma[c] * inv;
    scl[c] = ga;
    shf[c] = beta[c] - mean * ga;
}

// ---------------- fp16 tensor-core GEMM: Y = W[M,256] @ B[256,4096] -----------
#define GAW 20   // sA row stride: 16 data words (32 halves) + 4 pad
#define GBW 36   // sB row stride: 32 data words (64 halves) + 4 pad
__global__ __launch_bounds__(128) void gemm16_kernel(
    const float* __restrict__ W, const float* __restrict__ Bsrc,
    const float* __restrict__ bias, const float* __restrict__ res,
    float* __restrict__ Yout,
    __half* __restrict__ qh, __half* __restrict__ kh, __half* __restrict__ vh,
    const float* __restrict__ scl, const float* __restrict__ shf,
    float qscale, int mode) {
    __shared__ __align__(16) uint32_t sA[64 * GAW];
    __shared__ __align__(16) uint32_t sB[32 * GBW];
    __shared__ float sSc[C_DIM], sSh[C_DIM];
    __shared__ __align__(16) __half sH[64 * 72];

    const int tid  = threadIdx.x;
    const int warp = tid >> 5;
    const int lane = tid & 31;
    const int g    = lane >> 2;
    const int tg   = lane & 3;
    const int wrow = warp * 16;
    const int m0 = blockIdx.y * 64, n0 = blockIdx.x * 64;

    if (mode == 0) {
        #pragma unroll
        for (int i = tid; i < C_DIM; i += 128) { sSc[i] = scl[i]; sSh[i] = shf[i]; }
    }
    __syncthreads();

    // ldmatrix lane base addresses (loop-invariant)
    const int mi = lane >> 3, r = lane & 7;
    const uint32_t a_base = smem_u32(sA)
        + ((wrow + (mi & 1) * 8 + r) * GAW + (mi >> 1) * 4) * 4;
    const uint32_t b_base = smem_u32(sB)
        + (((mi & 1) * 8 + r) * GBW + (mi >> 1) * 4) * 4;

    float acc[8][4];
    #pragma unroll
    for (int nt = 0; nt < 8; nt++)
        #pragma unroll
        for (int j = 0; j < 4; j++) acc[nt][j] = 0.f;

    for (int k0 = 0; k0 < C_DIM; k0 += 32) {
        // ---- A tile: W[64m x 32k] fp32 -> fp16 ----
        {
            int m = tid & 63, hh = tid >> 6;
            #pragma unroll
            for (int j = 0; j < 2; j++) {
                int h = hh * 2 + j;
                const float* wp = &W[(m0 + m) * C_DIM + k0 + h * 8];
                float4 w0 = *(const float4*)wp;
                float4 w1 = *(const float4*)(wp + 4);
                uint4 pk;
                pk.x = pkh2(w0.x, w0.y); pk.y = pkh2(w0.z, w0.w);
                pk.z = pkh2(w1.x, w1.y); pk.w = pkh2(w1.z, w1.w);
                *(uint4*)&sA[m * GAW + h * 4] = pk;
            }
        }
        // ---- B tile: Bsrc[32k x 64n] fp32 -> fp16 (+affine mode0) ----
        #pragma unroll
        for (int p = 0; p < 4; p++) {
            int idx = p * 128 + tid;
            int k = idx >> 4, n4 = idx & 15;
            float4 v = *(const float4*)&Bsrc[(k0 + k) * N_TOK + n0 + n4 * 4];
            if (mode == 0) {
                float sc = sSc[k0 + k], sh = sSh[k0 + k];
                v.x = v.x * sc + sh; v.y = v.y * sc + sh;
                v.z = v.z * sc + sh; v.w = v.w * sc + sh;
            }
            uint2 pk;
            pk.x = pkh2(v.x, v.y); pk.y = pkh2(v.z, v.w);
            *(uint2*)&sB[k * GBW + n4 * 2] = pk;
        }
        __syncthreads();

        #pragma unroll
        for (int kc = 0; kc < 2; kc++) {
            uint32_t a0, a1, a2, a3;
            ldsm4(a0, a1, a2, a3, a_base + kc * 32);
            uint32_t bk = b_base + kc * 16 * GBW * 4;
            #pragma unroll
            for (int ns = 0; ns < 4; ns++) {
                uint32_t b00, b01, b10, b11;
                ldsm4t(b00, b01, b10, b11, bk + ns * 32);
                mma_f16(acc[2 * ns],     a0, a1, a2, a3, b00, b01);
                mma_f16(acc[2 * ns + 1], a0, a1, a2, a3, b10, b11);
            }
        }
        __syncthreads();
    }

    // ---- epilogue ----
    int mA = m0 + wrow + g, mB = mA + 8;
    float bv0 = bias[mA], bv1 = bias[mB];

    if (mode == 1) {
        #pragma unroll
        for (int nt = 0; nt < 8; nt++) {
            int n = n0 + nt * 8 + 2 * tg;
            Yout[mA * N_TOK + n]     = acc[nt][0] + bv0 + res[mA * N_TOK + n];
            Yout[mA * N_TOK + n + 1] = acc[nt][1] + bv0 + res[mA * N_TOK + n + 1];
            Yout[mB * N_TOK + n]     = acc[nt][2] + bv1 + res[mB * N_TOK + n];
            Yout[mB * N_TOK + n + 1] = acc[nt][3] + bv1 + res[mB * N_TOK + n + 1];
        }
        return;
    }

    // mode 0: fp16 QKV. Q rows (m<256) pre-scaled by qscale (scale*log2e).
    float q0s = (mA < C_DIM) ? qscale : 1.0f;
    float q1s = (mB < C_DIM) ? qscale : 1.0f;
    bool isV = (m0 >= 2 * C_DIM);
    int lmA = wrow + g, lmB = lmA + 8;
    #pragma unroll
    for (int nt = 0; nt < 8; nt++) {
        int ln = nt * 8 + 2 * tg;
        __half h00 = __float2half_rn((acc[nt][0] + bv0) * q0s);
        __half h01 = __float2half_rn((acc[nt][1] + bv0) * q0s);
        __half h10 = __float2half_rn((acc[nt][2] + bv1) * q1s);
        __half h11 = __float2half_rn((acc[nt][3] + bv1) * q1s);
        if (isV) {
            sH[lmA * 72 + ln] = h00; sH[lmA * 72 + ln + 1] = h01;
            sH[lmB * 72 + ln] = h10; sH[lmB * 72 + ln + 1] = h11;
        } else {
            sH[ln * 72 + lmA] = h00; sH[(ln + 1) * 72 + lmA] = h01;
            sH[ln * 72 + lmB] = h10; sH[(ln + 1) * 72 + lmB] = h11;
        }
    }
    __syncthreads();

    if (isV) {
        int chb = m0 - 2 * C_DIM;
        #pragma unroll
        for (int it = 0; it < 4; it++) {
            int i = it * 128 + tid;
            int chl = i >> 3, c = i & 7;
            uint4 v = *(const uint4*)&sH[chl * 72 + c * 8];
            *(uint4*)&vh[(chb + chl) * N_TOK + n0 + c * 8] = v;
        }
    } else {
        bool isQ = (m0 < C_DIM);
        __half* dst = isQ ? qh : kh;
        int mrel = isQ ? m0 : (m0 - C_DIM);
        #pragma unroll
        for (int it = 0; it < 4; it++) {
            int i = it * 128 + tid;
            int hl = i >> 8, t = (i >> 2) & 63, c = i & 3;
            uint4 v = *(const uint4*)&sH[t * 72 + hl * 32 + c * 8];
            int head = (mrel >> 5) + hl;
            *(uint4*)&dst[head * (N_TOK * HDIM) + (n0 + t) * HDIM + c * 8] = v;
        }
    }
}

// ---------------- Flash attention: double-buffered cp.async pipeline ----------
#define SKW 20    // sQ/sK row stride in 32-bit words (16 data + 4 pad)
#define SVW 36    // sV row stride in 32-bit words (32 data + 4 pad)
#define KBUF_B (64 * SKW * 4)    // K buffer stride in bytes
#define VBUF_B (HDIM * SVW * 4)  // V buffer stride in bytes
#define ONES2 0x3C003C00u        // half2(1.0, 1.0)
__global__ __launch_bounds__(128) void attn_kernel(const __half* __restrict__ qh,
                                                   const __half* __restrict__ kh,
                                                   const __half* __restrict__ vh,
                                                   float* __restrict__ po,
                                                   float* __restrict__ pl) {
    __shared__ __align__(16) uint32_t sQ2[64 * SKW];
    __shared__ __align__(16) uint32_t sK2[2 * 64 * SKW];
    __shared__ __align__(16) uint32_t sV2[2 * HDIM * SVW];

    const int tid  = threadIdx.x;
    const int warp = tid >> 5;
    const int lane = tid & 31;
    const int g    = lane >> 2;
    const int tg   = lane & 3;
    const int head  = blockIdx.y;
    const int split = blockIdx.z;
    const int q0   = blockIdx.x * 64;
    const int wrow = warp * 16;

    const __half* Qp = qh + head * (N_TOK * HDIM);
    const __half* Kp = kh + head * (N_TOK * HDIM);
    const __half* Vp = vh + head * (HDIM * N_TOK);

    const uint32_t ksm = smem_u32(sK2);
    const uint32_t vsm = smem_u32(sV2);

    // per-thread load slots (2 x 16B for K, 2 x 16B for V)
    const int kt0 = tid >> 2,          kc0 = tid & 3;
    const int kt1 = (128 + tid) >> 2,  kc1 = tid & 3;          // (128+tid)&3 == tid&3
    const int vd0 = tid >> 3,          vc0 = tid & 7;
    const int vd1 = (128 + tid) >> 3,  vc1 = tid & 7;
    const uint32_t kdst0 = (kt0 * SKW + kc0 * 4) * 4;
    const uint32_t kdst1 = (kt1 * SKW + kc1 * 4) * 4;
    const uint32_t vdst0 = (vd0 * SVW + vc0 * 4) * 4;
    const uint32_t vdst1 = (vd1 * SVW + vc1 * 4) * 4;

    // ---- precompute ldmatrix lane base addresses (buffer 0) ----
    const int mi = lane >> 3, r = lane & 7;
    uint32_t base_k[4], base_v[2];
    #pragma unroll
    for (int j = 0; j < 4; j++) {
        int key = (2 * j + (mi >> 1)) * 8 + r;
        base_k[j] = ksm + (key * SKW + (mi & 1) * 4) * 4;
    }
    #pragma unroll
    for (int jj = 0; jj < 2; jj++) {
        int d = (2 * jj + (mi >> 1)) * 8 + r;
        base_v[jj] = vsm + (d * SVW + (mi & 1) * 4) * 4;
    }

    // ---- Q tile (synchronous, once) ----
    #pragma unroll
    for (int it = 0; it < 2; it++) {
        int i = it * 128 + tid;
        int t = i >> 2, c = i & 3;
        uint4 v = *(const uint4*)&Qp[(q0 + t) * HDIM + c * 8];
        *(uint4*)&sQ2[t * SKW + c * 4] = v;
    }

    const int kbase0 = split * KEYS_PER_SPLIT;
    const int NT = KEYS_PER_SPLIT / 64;     // 16 tiles

    // ---- prologue: async-load tile 0 into buffer 0 ----
    cp16(ksm + kdst0, &Kp[(kbase0 + kt0) * HDIM + kc0 * 8]);
    cp16(ksm + kdst1, &Kp[(kbase0 + kt1) * HDIM + kc1 * 8]);
    cp16(vsm + vdst0, &Vp[vd0 * N_TOK + kbase0 + vc0 * 8]);
    cp16(vsm + vdst1, &Vp[vd1 * N_TOK + kbase0 + vc1 * 8]);
    cp_commit();

    __syncthreads();   // sQ ready

    uint32_t qa[2][4];
    #pragma unroll
    for (int ks = 0; ks < 2; ks++) {
        qa[ks][0] = sQ2[(wrow + g)     * SKW + ks * 8 + tg];
        qa[ks][1] = sQ2[(wrow + g + 8) * SKW + ks * 8 + tg];
        qa[ks][2] = sQ2[(wrow + g)     * SKW + ks * 8 + tg + 4];
        qa[ks][3] = sQ2[(wrow + g + 8) * SKW + ks * 8 + tg + 4];
    }

    float o[4][4];
    #pragma unroll
    for (int nt = 0; nt < 4; nt++)
        #pragma unroll
        for (int j = 0; j < 4; j++) o[nt][j] = 0.f;
    float lsum[4] = {0.f, 0.f, 0.f, 0.f};

    for (int t = 0; t < NT; t++) {
        const int buf = t & 1;
        if (t + 1 < NT) {
            // issue next tile into alternate buffer
            const int kn = kbase0 + (t + 1) * 64;
            const uint32_t kb = (uint32_t)((buf ^ 1) * KBUF_B);
            const uint32_t vb = (uint32_t)((buf ^ 1) * VBUF_B);
            cp16(ksm + kb + kdst0, &Kp[(kn + kt0) * HDIM + kc0 * 8]);
            cp16(ksm + kb + kdst1, &Kp[(kn + kt1) * HDIM + kc1 * 8]);
            cp16(vsm + vb + vdst0, &Vp[vd0 * N_TOK + kn + vc0 * 8]);
            cp16(vsm + vb + vdst1, &Vp[vd1 * N_TOK + kn + vc1 * 8]);
            cp_commit();
            cp_wait<1>();   // tile t complete
        } else {
            cp_wait<0>();
        }
        __syncthreads();

        const uint32_t kb = (uint32_t)(buf * KBUF_B);
        const uint32_t vb = (uint32_t)(buf * VBUF_B);

        // ---- phase 1: S[16 x 64] = Q . K^T ----
        float s[8][4];
        #pragma unroll
        for (int nt = 0; nt < 8; nt++)
            #pragma unroll
            for (int j = 0; j < 4; j++) s[nt][j] = 0.f;
        #pragma unroll
        for (int ks = 0; ks < 2; ks++) {
            #pragma unroll
            for (int j = 0; j < 4; j++) {
                uint32_t b00, b01, b10, b11;
                ldsm4(b00, b01, b10, b11, base_k[j] + kb + ks * 32);
                mma_f16(s[2*j],   qa[ks][0], qa[ks][1], qa[ks][2], qa[ks][3], b00, b01);
                mma_f16(s[2*j+1], qa[ks][0], qa[ks][1], qa[ks][2], qa[ks][3], b10, b11);
            }
        }

        // ---- zero-shift exp via f16x2 MUFU, straight into A fragments ----
        uint32_t pa[4][4];
        #pragma unroll
        for (int nt = 0; nt < 8; nt++) {
            uint32_t lo = h2exp2(s[nt][0], s[nt][1]);
            uint32_t hi = h2exp2(s[nt][2], s[nt][3]);
            pa[nt >> 1][(nt & 1) * 2 + 0] = lo;
            pa[nt >> 1][(nt & 1) * 2 + 1] = hi;
        }

        // ---- phase 3: O += P.V  and  l += P.1 ----
        #pragma unroll
        for (int ks = 0; ks < 4; ks++) {
            #pragma unroll
            for (int jj = 0; jj < 2; jj++) {
                uint32_t b00, b01, b10, b11;
                ldsm4(b00, b01, b10, b11, base_v[jj] + vb + ks * 32);
                mma_f16(o[2*jj],   pa[ks][0], pa[ks][1], pa[ks][2], pa[ks][3], b00, b01);
                mma_f16(o[2*jj+1], pa[ks][0], pa[ks][1], pa[ks][2], pa[ks][3], b10, b11);
            }
            mma_f16(lsum, pa[ks][0], pa[ks][1], pa[ks][2], pa[ks][3], ONES2, ONES2);
        }
        __syncthreads();   // all warps done with buf before it is refilled
    }

    const int sidx = split * HEADS + head;
    int qA = q0 + wrow + g;
    int qB = qA + 8;
    if (tg == 0) {
        pl[sidx * N_TOK + qA] = lsum[0];
        pl[sidx * N_TOK + qB] = lsum[2];
    }
    // po token-major: po[(sidx*N_TOK + q)*HDIM + d]
    float* pobA = po + ((size_t)sidx * N_TOK + qA) * HDIM;
    float* pobB = po + ((size_t)sidx * N_TOK + qB) * HDIM;
    #pragma unroll
    for (int nt = 0; nt < 4; nt++) {
        int d = nt * 8 + 2 * tg;
        *(float2*)&pobA[d] = make_float2(o[nt][0], o[nt][1]);
        *(float2*)&pobB[d] = make_float2(o[nt][2], o[nt][3]);
    }
}

// ---------------- combine split-KV partials (zero-shift: plain sums) ----------
__global__ void attn_combine_kernel(const float* __restrict__ po,
                                    const float* __restrict__ pl,
                                    float* __restrict__ outp) {
    int gid  = blockIdx.x * 256 + threadIdx.x;   // 0..32767
    int head = gid >> 12;
    int qi   = gid & (N_TOK - 1);

    float L = 0.f;
    #pragma unroll
    for (int i = 0; i < SPLIT; i++)
        L += pl[(i * HEADS + head) * N_TOK + qi];
    float inv = 1.f / L;

    float acc[HDIM];
    #pragma unroll
    for (int d = 0; d < HDIM; d++) acc[d] = 0.f;
    #pragma unroll
    for (int i = 0; i < SPLIT; i++) {
        const float* src = po + (((size_t)(i * HEADS + head)) * N_TOK + qi) * HDIM;
        #pragma unroll
        for (int d4 = 0; d4 < HDIM; d4 += 4) {
            float4 v = *(const float4*)&src[d4];
            acc[d4]     += v.x;
            acc[d4 + 1] += v.y;
            acc[d4 + 2] += v.z;
            acc[d4 + 3] += v.w;
        }
    }
    #pragma unroll
    for (int d = 0; d < HDIM; d++)
        outp[(head * HDIM + d) * N_TOK + qi] = acc[d] * inv;
}

// ---------------- launcher ----------------------------------------------------
extern "C" void kernel_launch(void* const* d_in, const int* in_sizes, int n_in,
                              void* d_out, int out_size) {
    const float* x      = (const float*)d_in[0];
    const float* gamma  = (const float*)d_in[1];
    const float* beta   = (const float*)d_in[2];
    const float* qkv_w  = (const float*)d_in[3];
    const float* qkv_b  = (const float*)d_in[4];
    const float* proj_w = (const float*)d_in[5];
    const float* proj_b = (const float*)d_in[6];
    float* out = (float*)d_out;

    float *p_part, *p_scale, *p_shift, *p_attn, *p_po, *p_pl;
    __half *p_qh, *p_kh, *p_vh;
    cudaGetSymbolAddress((void**)&p_part,  g_part);
    cudaGetSymbolAddress((void**)&p_scale, g_scale);
    cudaGetSymbolAddress((void**)&p_shift, g_shift);
    cudaGetSymbolAddress((void**)&p_qh,    g_qh);
    cudaGetSymbolAddress((void**)&p_kh,    g_kh);
    cudaGetSymbolAddress((void**)&p_vh,    g_vh);
    cudaGetSymbolAddress((void**)&p_attn,  g_attn);
    cudaGetSymbolAddress((void**)&p_po,    g_po);
    cudaGetSymbolAddress((void**)&p_pl,    g_pl);

    // 1/sqrt(32) * log2(e): scores come out in log2 domain
    const float qscale = 0.17677669529663687f * 1.44269504088896340f;

    // 1. GroupNorm stats + per-channel scale/shift
    gn_stats_kernel<<<GROUPS * GN_SL, 256>>>(x, p_part);
    gn_final_kernel<<<1, 256>>>(p_part, gamma, beta, p_scale, p_shift);

    // 2. QKV GEMM (fp16 MMA + ldmatrix, fused GN affine, fp16 outputs)
    gemm16_kernel<<<dim3(N_TOK / 64, (3 * C_DIM) / 64), 128>>>(
        qkv_w, x, qkv_b, nullptr, nullptr,
        p_qh, p_kh, p_vh, p_scale, p_shift, qscale, 0);

    // 3. Attention: fp16 flash kernel (cp.async double-buffered), split-KV x4
    attn_kernel<<<dim3(N_TOK / 64, HEADS, SPLIT), 128>>>(
        p_qh, p_kh, p_vh, p_po, p_pl);
    attn_combine_kernel<<<(N_TOK * HEADS) / 256, 256>>>(p_po, p_pl, p_attn);

    // 4. Proj GEMM (fp16 MMA) + bias + residual -> d_out
    gemm16_kernel<<<dim3(N_TOK / 64, C_DIM / 64), 128>>>(
        proj_w, p_attn, proj_b, x, out,
        nullptr, nullptr, nullptr, p_scale, p_shift, 1.0f, 1);
}

// round 17
// speedup vs baseline: 1.3783x; 1.1901x over previous
#include <cuda_runtime.h>
#include <cuda_fp16.h>
#include <math.h>
#include <stdint.h>

// Problem constants
#define C_DIM   256
#define N_TOK   4096
#define GROUPS  8
#define CPG     (C_DIM / GROUPS)        // 32
#define HEADS   8
#define HDIM    32
#define EPSV    1e-5f
#define GSIZE   (CPG * N_TOK)           // 131072 elems per group
#define SPLIT   4
#define KEYS_PER_SPLIT (N_TOK / SPLIT)  // 1024
#define GN_SL   32                      // gn_stats slices per group

// ---------------- scratch (static device globals; no allocation) -------------
__device__ float  g_part[GROUPS * GN_SL][2];  // groupnorm partial (sum, sumsq)
__device__ float  g_scale[C_DIM];             // per-channel gn scale
__device__ float  g_shift[C_DIM];             // per-channel gn shift
__device__ __half g_wqh[3 * C_DIM * C_DIM];   // qkv_w fp16
__device__ __half g_wph[C_DIM * C_DIM];       // proj_w fp16
__device__ __half g_hh[C_DIM * N_TOK];        // groupnorm output fp16 [C][N]
__device__ __half g_qh[HEADS * N_TOK * HDIM]; // Q fp16, token-major, pre-scaled (incl log2e)
__device__ __half g_kh[HEADS * N_TOK * HDIM]; // K fp16, token-major
__device__ __half g_vh[HEADS * HDIM * N_TOK]; // V fp16, dim-major
__device__ __half g_attn[C_DIM * N_TOK];      // combined attention output fp16 [C][N]
__device__ float  g_po[SPLIT * HEADS * N_TOK * HDIM]; // partial o [sidx][q][d]
__device__ float  g_pl[SPLIT * HEADS * N_TOK];        // partial denom

// ---------------- mma / ldmatrix / cp.async / exp helpers ---------------------
__device__ __forceinline__ void mma_f16(float* d,
                                        uint32_t a0, uint32_t a1, uint32_t a2, uint32_t a3,
                                        uint32_t b0, uint32_t b1) {
    asm volatile(
        "mma.sync.aligned.m16n8k16.row.col.f32.f16.f16.f32 "
        "{%0,%1,%2,%3}, {%4,%5,%6,%7}, {%8,%9}, {%0,%1,%2,%3};\n"
        : "+f"(d[0]), "+f"(d[1]), "+f"(d[2]), "+f"(d[3])
        : "r"(a0), "r"(a1), "r"(a2), "r"(a3), "r"(b0), "r"(b1));
}
__device__ __forceinline__ void ldsm4(uint32_t& r0, uint32_t& r1, uint32_t& r2,
                                      uint32_t& r3, uint32_t addr) {
    asm volatile("ldmatrix.sync.aligned.m8n8.x4.shared.b16 {%0,%1,%2,%3}, [%4];"
                 : "=r"(r0), "=r"(r1), "=r"(r2), "=r"(r3) : "r"(addr));
}
__device__ __forceinline__ void ldsm4t(uint32_t& r0, uint32_t& r1, uint32_t& r2,
                                       uint32_t& r3, uint32_t addr) {
    asm volatile("ldmatrix.sync.aligned.m8n8.x4.trans.shared.b16 {%0,%1,%2,%3}, [%4];"
                 : "=r"(r0), "=r"(r1), "=r"(r2), "=r"(r3) : "r"(addr));
}
__device__ __forceinline__ uint32_t smem_u32(const void* p) {
    return (uint32_t)__cvta_generic_to_shared(p);
}
__device__ __forceinline__ void cp16(uint32_t dst, const void* src) {
    asm volatile("cp.async.cg.shared.global [%0], [%1], 16;" :: "r"(dst), "l"(src));
}
__device__ __forceinline__ void cp_commit() {
    asm volatile("cp.async.commit_group;");
}
template <int N> __device__ __forceinline__ void cp_wait() {
    asm volatile("cp.async.wait_group %0;" :: "n"(N));
}
__device__ __forceinline__ uint32_t h2exp2(float lo, float hi) {
    uint32_t h, r;
    asm("cvt.rn.f16x2.f32 %0, %1, %2;" : "=r"(h) : "f"(hi), "f"(lo));
    asm("ex2.approx.f16x2 %0, %1;" : "=r"(r) : "r"(h));
    return r;
}
__device__ __forceinline__ uint32_t pkh2(float a, float b) {
    __half2 h = __floats2half2_rn(a, b);
    return *(uint32_t*)&h;
}

// ---------------- GroupNorm: partial stats (256 blocks) ------------------------
__global__ void gn_stats_kernel(const float* __restrict__ x, float* __restrict__ part) {
    int g  = blockIdx.x >> 5;
    int sl = blockIdx.x & 31;
    const float* xg = x + g * GSIZE + sl * (GSIZE / GN_SL);
    float s = 0.f, ss = 0.f;
    for (int i = threadIdx.x; i < GSIZE / GN_SL; i += 256) {
        float v = xg[i];
        s += v; ss += v * v;
    }
    for (int o = 16; o > 0; o >>= 1) {
        s  += __shfl_down_sync(0xffffffff, s,  o);
        ss += __shfl_down_sync(0xffffffff, ss, o);
    }
    __shared__ float rs[8], rss[8];
    int wid = threadIdx.x >> 5, lid = threadIdx.x & 31;
    if (lid == 0) { rs[wid] = s; rss[wid] = ss; }
    __syncthreads();
    if (threadIdx.x == 0) {
        float ts = 0.f, tss = 0.f;
        #pragma unroll
        for (int w = 0; w < 8; w++) { ts += rs[w]; tss += rss[w]; }
        part[blockIdx.x * 2 + 0] = ts;
        part[blockIdx.x * 2 + 1] = tss;
    }
}

// ---------------- GroupNorm: finalize per-channel scale/shift -----------------
__global__ void gn_final_kernel(const float* __restrict__ part,
                                const float* __restrict__ gamma,
                                const float* __restrict__ beta,
                                float* __restrict__ scl, float* __restrict__ shf) {
    int c = threadIdx.x;           // 256 threads
    int g = c >> 5;
    float s = 0.f, ss = 0.f;
    #pragma unroll
    for (int t = 0; t < GN_SL; t++) {
        s  += part[(g * GN_SL + t) * 2 + 0];
        ss += part[(g * GN_SL + t) * 2 + 1];
    }
    float mean = s * (1.0f / GSIZE);
    float var  = ss * (1.0f / GSIZE) - mean * mean;
    float inv  = rsqrtf(var + EPSV);
    float ga   = gamma[c] * inv;
    scl[c] = ga;
    shf[c] = beta[c] - mean * ga;
}

// ---------------- weight fp32 -> fp16 conversion (once per call) ---------------
__global__ void conv_w_kernel(const float* __restrict__ qkv_w,
                              const float* __restrict__ proj_w,
                              __half* __restrict__ wq, __half* __restrict__ wp) {
    int i = blockIdx.x * 256 + threadIdx.x;   // 0..65535 float4 chunks
    if (i < 49152) {
        float4 v = ((const float4*)qkv_w)[i];
        uint2 pk; pk.x = pkh2(v.x, v.y); pk.y = pkh2(v.z, v.w);
        ((uint2*)wq)[i] = pk;
    } else {
        int j = i - 49152;
        float4 v = ((const float4*)proj_w)[j];
        uint2 pk; pk.x = pkh2(v.x, v.y); pk.y = pkh2(v.z, v.w);
        ((uint2*)wp)[j] = pk;
    }
}

// ---------------- GroupNorm: normalize + affine -> fp16 -----------------------
__global__ void gn_half_kernel(const float* __restrict__ x,
                               const float* __restrict__ scl,
                               const float* __restrict__ shf,
                               __half* __restrict__ hh) {
    int idx4 = blockIdx.x * 256 + threadIdx.x;  // 0..262143 float4
    int c = idx4 >> 10;                         // 1024 float4 per channel
    float sc = scl[c], sh = shf[c];
    float4 v = ((const float4*)x)[idx4];
    uint2 pk;
    pk.x = pkh2(v.x * sc + sh, v.y * sc + sh);
    pk.y = pkh2(v.z * sc + sh, v.w * sc + sh);
    ((uint2*)hh)[idx4] = pk;
}

// ---------------- fp16 tensor-core GEMM (cp.async 2-stage) --------------------
// Y = W[M,256] @ B[256,4096]; W, B fp16 in global.
// mode 0: fp16 Q(scaled)/K/V outputs via smem repack.  mode 1: fp32 + bias + res.
#define GAW 20   // sA row stride words (16 data + 4 pad)
#define GBW 36   // sB row stride words (32 data + 4 pad)
#define GA_STG (64 * GAW)   // words per A stage
#define GB_STG (32 * GBW)   // words per B stage
__global__ __launch_bounds__(128) void gemm16_kernel(
    const __half* __restrict__ W, const __half* __restrict__ Bsrc,
    const float* __restrict__ bias, const float* __restrict__ res,
    float* __restrict__ Yout,
    __half* __restrict__ qh, __half* __restrict__ kh, __half* __restrict__ vh,
    float qscale, int mode) {
    __shared__ __align__(16) uint32_t sA[2 * GA_STG];
    __shared__ __align__(16) uint32_t sB[2 * GB_STG];
    __shared__ __align__(16) __half sH[64 * 72];

    const int tid  = threadIdx.x;
    const int warp = tid >> 5;
    const int lane = tid & 31;
    const int g    = lane >> 2;
    const int tg   = lane & 3;
    const int wrow = warp * 16;
    const int m0 = blockIdx.y * 64, n0 = blockIdx.x * 64;

    const uint32_t asm_ = smem_u32(sA);
    const uint32_t bsm  = smem_u32(sB);

    // cp.async slots: A 256 chunks (2/thread), B 256 chunks (2/thread)
    const int am0 = tid >> 1,          ac0 = (tid & 1) * 2;       // m, 16B-chunk base
    const int bk0 = tid >> 2,          bc0 = (tid & 3) * 2;       // k, 16B-chunk base
    // per-thread: A chunks (am0, ac0) and (am0, ac0+1); B chunks (bk0,bc0),(bk0,bc0+1)

    // ldmatrix lane base addresses (stage 0)
    const int mi = lane >> 3, r = lane & 7;
    const uint32_t a_base = asm_
        + ((wrow + (mi & 1) * 8 + r) * GAW + (mi >> 1) * 4) * 4;
    const uint32_t b_base = bsm
        + (((mi & 1) * 8 + r) * GBW + (mi >> 1) * 4) * 4;

    float acc[8][4];
    #pragma unroll
    for (int nt = 0; nt < 8; nt++)
        #pragma unroll
        for (int j = 0; j < 4; j++) acc[nt][j] = 0.f;

    // prologue: stage 0 <- k0 = 0
    {
        cp16(asm_ + ((am0 * GAW + ac0 * 4) * 4),       &W[(m0 + am0) * C_DIM + ac0 * 8]);
        cp16(asm_ + ((am0 * GAW + (ac0 + 1) * 4) * 4), &W[(m0 + am0) * C_DIM + (ac0 + 1) * 8]);
        cp16(bsm + ((bk0 * GBW + bc0 * 4) * 4),        &Bsrc[bk0 * N_TOK + n0 + bc0 * 8]);
        cp16(bsm + ((bk0 * GBW + (bc0 + 1) * 4) * 4),  &Bsrc[bk0 * N_TOK + n0 + (bc0 + 1) * 8]);
        cp_commit();
    }

    for (int it = 0; it < 8; it++) {
        const int buf = it & 1;
        if (it < 7) {
            const int kn = (it + 1) * 32;
            const uint32_t ao = (uint32_t)((buf ^ 1) * GA_STG * 4);
            const uint32_t bo = (uint32_t)((buf ^ 1) * GB_STG * 4);
            cp16(asm_ + ao + ((am0 * GAW + ac0 * 4) * 4),       &W[(m0 + am0) * C_DIM + kn + ac0 * 8]);
            cp16(asm_ + ao + ((am0 * GAW + (ac0 + 1) * 4) * 4), &W[(m0 + am0) * C_DIM + kn + (ac0 + 1) * 8]);
            cp16(bsm + bo + ((bk0 * GBW + bc0 * 4) * 4),        &Bsrc[(kn + bk0) * N_TOK + n0 + bc0 * 8]);
            cp16(bsm + bo + ((bk0 * GBW + (bc0 + 1) * 4) * 4),  &Bsrc[(kn + bk0) * N_TOK + n0 + (bc0 + 1) * 8]);
            cp_commit();
            cp_wait<1>();
        } else {
            cp_wait<0>();
        }
        __syncthreads();

        const uint32_t ao = (uint32_t)(buf * GA_STG * 4);
        const uint32_t bo = (uint32_t)(buf * GB_STG * 4);
        #pragma unroll
        for (int kc = 0; kc < 2; kc++) {
            uint32_t a0, a1, a2, a3;
            ldsm4(a0, a1, a2, a3, a_base + ao + kc * 32);
            uint32_t bk = b_base + bo + kc * 16 * GBW * 4;
            #pragma unroll
            for (int ns = 0; ns < 4; ns++) {
                uint32_t b00, b01, b10, b11;
                ldsm4t(b00, b01, b10, b11, bk + ns * 32);
                mma_f16(acc[2 * ns],     a0, a1, a2, a3, b00, b01);
                mma_f16(acc[2 * ns + 1], a0, a1, a2, a3, b10, b11);
            }
        }
        __syncthreads();
    }

    // ---- epilogue ----
    int mA = m0 + wrow + g, mB = mA + 8;
    float bv0 = bias[mA], bv1 = bias[mB];

    if (mode == 1) {
        #pragma unroll
        for (int nt = 0; nt < 8; nt++) {
            int n = n0 + nt * 8 + 2 * tg;
            Yout[mA * N_TOK + n]     = acc[nt][0] + bv0 + res[mA * N_TOK + n];
            Yout[mA * N_TOK + n + 1] = acc[nt][1] + bv0 + res[mA * N_TOK + n + 1];
            Yout[mB * N_TOK + n]     = acc[nt][2] + bv1 + res[mB * N_TOK + n];
            Yout[mB * N_TOK + n + 1] = acc[nt][3] + bv1 + res[mB * N_TOK + n + 1];
        }
        return;
    }

    // mode 0: fp16 QKV. Q rows (m<256) pre-scaled by qscale (scale*log2e).
    float q0s = (mA < C_DIM) ? qscale : 1.0f;
    float q1s = (mB < C_DIM) ? qscale : 1.0f;
    bool isV = (m0 >= 2 * C_DIM);
    int lmA = wrow + g, lmB = lmA + 8;
    #pragma unroll
    for (int nt = 0; nt < 8; nt++) {
        int ln = nt * 8 + 2 * tg;
        __half h00 = __float2half_rn((acc[nt][0] + bv0) * q0s);
        __half h01 = __float2half_rn((acc[nt][1] + bv0) * q0s);
        __half h10 = __float2half_rn((acc[nt][2] + bv1) * q1s);
        __half h11 = __float2half_rn((acc[nt][3] + bv1) * q1s);
        if (isV) {
            sH[lmA * 72 + ln] = h00; sH[lmA * 72 + ln + 1] = h01;
            sH[lmB * 72 + ln] = h10; sH[lmB * 72 + ln + 1] = h11;
        } else {
            sH[ln * 72 + lmA] = h00; sH[(ln + 1) * 72 + lmA] = h01;
            sH[ln * 72 + lmB] = h10; sH[(ln + 1) * 72 + lmB] = h11;
        }
    }
    __syncthreads();

    if (isV) {
        int chb = m0 - 2 * C_DIM;
        #pragma unroll
        for (int it = 0; it < 4; it++) {
            int i = it * 128 + tid;
            int chl = i >> 3, c = i & 7;
            uint4 v = *(const uint4*)&sH[chl * 72 + c * 8];
            *(uint4*)&vh[(chb + chl) * N_TOK + n0 + c * 8] = v;
        }
    } else {
        bool isQ = (m0 < C_DIM);
        __half* dst = isQ ? qh : kh;
        int mrel = isQ ? m0 : (m0 - C_DIM);
        #pragma unroll
        for (int it = 0; it < 4; it++) {
            int i = it * 128 + tid;
            int hl = i >> 8, t = (i >> 2) & 63, c = i & 3;
            uint4 v = *(const uint4*)&sH[t * 72 + hl * 32 + c * 8];
            int head = (mrel >> 5) + hl;
            *(uint4*)&dst[head * (N_TOK * HDIM) + (n0 + t) * HDIM + c * 8] = v;
        }
    }
}

// ---------------- Flash attention: double-buffered cp.async pipeline ----------
#define SKW 20    // sQ/sK row stride in 32-bit words (16 data + 4 pad)
#define SVW 36    // sV row stride in 32-bit words (32 data + 4 pad)
#define KBUF_B (64 * SKW * 4)    // K buffer stride in bytes
#define VBUF_B (HDIM * SVW * 4)  // V buffer stride in bytes
#define ONES2 0x3C003C00u        // half2(1.0, 1.0)
__global__ __launch_bounds__(128) void attn_kernel(const __half* __restrict__ qh,
                                                   const __half* __restrict__ kh,
                                                   const __half* __restrict__ vh,
                                                   float* __restrict__ po,
                                                   float* __restrict__ pl) {
    __shared__ __align__(16) uint32_t sQ2[64 * SKW];
    __shared__ __align__(16) uint32_t sK2[2 * 64 * SKW];
    __shared__ __align__(16) uint32_t sV2[2 * HDIM * SVW];

    const int tid  = threadIdx.x;
    const int warp = tid >> 5;
    const int lane = tid & 31;
    const int g    = lane >> 2;
    const int tg   = lane & 3;
    const int head  = blockIdx.y;
    const int split = blockIdx.z;
    const int q0   = blockIdx.x * 64;
    const int wrow = warp * 16;

    const __half* Qp = qh + head * (N_TOK * HDIM);
    const __half* Kp = kh + head * (N_TOK * HDIM);
    const __half* Vp = vh + head * (HDIM * N_TOK);

    const uint32_t ksm = smem_u32(sK2);
    const uint32_t vsm = smem_u32(sV2);

    const int kt0 = tid >> 2,          kc0 = tid & 3;
    const int kt1 = (128 + tid) >> 2,  kc1 = tid & 3;
    const int vd0 = tid >> 3,          vc0 = tid & 7;
    const int vd1 = (128 + tid) >> 3,  vc1 = tid & 7;
    const uint32_t kdst0 = (kt0 * SKW + kc0 * 4) * 4;
    const uint32_t kdst1 = (kt1 * SKW + kc1 * 4) * 4;
    const uint32_t vdst0 = (vd0 * SVW + vc0 * 4) * 4;
    const uint32_t vdst1 = (vd1 * SVW + vc1 * 4) * 4;

    const int mi = lane >> 3, r = lane & 7;
    uint32_t base_k[4], base_v[2];
    #pragma unroll
    for (int j = 0; j < 4; j++) {
        int key = (2 * j + (mi >> 1)) * 8 + r;
        base_k[j] = ksm + (key * SKW + (mi & 1) * 4) * 4;
    }
    #pragma unroll
    for (int jj = 0; jj < 2; jj++) {
        int d = (2 * jj + (mi >> 1)) * 8 + r;
        base_v[jj] = vsm + (d * SVW + (mi & 1) * 4) * 4;
    }

    #pragma unroll
    for (int it = 0; it < 2; it++) {
        int i = it * 128 + tid;
        int t = i >> 2, c = i & 3;
        uint4 v = *(const uint4*)&Qp[(q0 + t) * HDIM + c * 8];
        *(uint4*)&sQ2[t * SKW + c * 4] = v;
    }

    const int kbase0 = split * KEYS_PER_SPLIT;
    const int NT = KEYS_PER_SPLIT / 64;     // 16 tiles

    cp16(ksm + kdst0, &Kp[(kbase0 + kt0) * HDIM + kc0 * 8]);
    cp16(ksm + kdst1, &Kp[(kbase0 + kt1) * HDIM + kc1 * 8]);
    cp16(vsm + vdst0, &Vp[vd0 * N_TOK + kbase0 + vc0 * 8]);
    cp16(vsm + vdst1, &Vp[vd1 * N_TOK + kbase0 + vc1 * 8]);
    cp_commit();

    __syncthreads();

    uint32_t qa[2][4];
    #pragma unroll
    for (int ks = 0; ks < 2; ks++) {
        qa[ks][0] = sQ2[(wrow + g)     * SKW + ks * 8 + tg];
        qa[ks][1] = sQ2[(wrow + g + 8) * SKW + ks * 8 + tg];
        qa[ks][2] = sQ2[(wrow + g)     * SKW + ks * 8 + tg + 4];
        qa[ks][3] = sQ2[(wrow + g + 8) * SKW + ks * 8 + tg + 4];
    }

    float o[4][4];
    #pragma unroll
    for (int nt = 0; nt < 4; nt++)
        #pragma unroll
        for (int j = 0; j < 4; j++) o[nt][j] = 0.f;
    float lsum[4] = {0.f, 0.f, 0.f, 0.f};

    for (int t = 0; t < NT; t++) {
        const int buf = t & 1;
        if (t + 1 < NT) {
            const int kn = kbase0 + (t + 1) * 64;
            const uint32_t kb = (uint32_t)((buf ^ 1) * KBUF_B);
            const uint32_t vb = (uint32_t)((buf ^ 1) * VBUF_B);
            cp16(ksm + kb + kdst0, &Kp[(kn + kt0) * HDIM + kc0 * 8]);
            cp16(ksm + kb + kdst1, &Kp[(kn + kt1) * HDIM + kc1 * 8]);
            cp16(vsm + vb + vdst0, &Vp[vd0 * N_TOK + kn + vc0 * 8]);
            cp16(vsm + vb + vdst1, &Vp[vd1 * N_TOK + kn + vc1 * 8]);
            cp_commit();
            cp_wait<1>();
        } else {
            cp_wait<0>();
        }
        __syncthreads();

        const uint32_t kb = (uint32_t)(buf * KBUF_B);
        const uint32_t vb = (uint32_t)(buf * VBUF_B);

        float s[8][4];
        #pragma unroll
        for (int nt = 0; nt < 8; nt++)
            #pragma unroll
            for (int j = 0; j < 4; j++) s[nt][j] = 0.f;
        #pragma unroll
        for (int ks = 0; ks < 2; ks++) {
            #pragma unroll
            for (int j = 0; j < 4; j++) {
                uint32_t b00, b01, b10, b11;
                ldsm4(b00, b01, b10, b11, base_k[j] + kb + ks * 32);
                mma_f16(s[2*j],   qa[ks][0], qa[ks][1], qa[ks][2], qa[ks][3], b00, b01);
                mma_f16(s[2*j+1], qa[ks][0], qa[ks][1], qa[ks][2], qa[ks][3], b10, b11);
            }
        }

        uint32_t pa[4][4];
        #pragma unroll
        for (int nt = 0; nt < 8; nt++) {
            uint32_t lo = h2exp2(s[nt][0], s[nt][1]);
            uint32_t hi = h2exp2(s[nt][2], s[nt][3]);
            pa[nt >> 1][(nt & 1) * 2 + 0] = lo;
            pa[nt >> 1][(nt & 1) * 2 + 1] = hi;
        }

        #pragma unroll
        for (int ks = 0; ks < 4; ks++) {
            #pragma unroll
            for (int jj = 0; jj < 2; jj++) {
                uint32_t b00, b01, b10, b11;
                ldsm4(b00, b01, b10, b11, base_v[jj] + vb + ks * 32);
                mma_f16(o[2*jj],   pa[ks][0], pa[ks][1], pa[ks][2], pa[ks][3], b00, b01);
                mma_f16(o[2*jj+1], pa[ks][0], pa[ks][1], pa[ks][2], pa[ks][3], b10, b11);
            }
            mma_f16(lsum, pa[ks][0], pa[ks][1], pa[ks][2], pa[ks][3], ONES2, ONES2);
        }
        __syncthreads();
    }

    const int sidx = split * HEADS + head;
    int qA = q0 + wrow + g;
    int qB = qA + 8;
    if (tg == 0) {
        pl[sidx * N_TOK + qA] = lsum[0];
        pl[sidx * N_TOK + qB] = lsum[2];
    }
    float* pobA = po + ((size_t)sidx * N_TOK + qA) * HDIM;
    float* pobB = po + ((size_t)sidx * N_TOK + qB) * HDIM;
    #pragma unroll
    for (int nt = 0; nt < 4; nt++) {
        int d = nt * 8 + 2 * tg;
        *(float2*)&pobA[d] = make_float2(o[nt][0], o[nt][1]);
        *(float2*)&pobB[d] = make_float2(o[nt][2], o[nt][3]);
    }
}

// ---------------- combine split-KV partials -> fp16 ---------------------------
__global__ void attn_combine_kernel(const float* __restrict__ po,
                                    const float* __restrict__ pl,
                                    __half* __restrict__ outp) {
    int gid  = blockIdx.x * 256 + threadIdx.x;   // 0..32767
    int head = gid >> 12;
    int qi   = gid & (N_TOK - 1);

    float L = 0.f;
    #pragma unroll
    for (int i = 0; i < SPLIT; i++)
        L += pl[(i * HEADS + head) * N_TOK + qi];
    float inv = 1.f / L;

    float acc[HDIM];
    #pragma unroll
    for (int d = 0; d < HDIM; d++) acc[d] = 0.f;
    #pragma unroll
    for (int i = 0; i < SPLIT; i++) {
        const float* src = po + (((size_t)(i * HEADS + head)) * N_TOK + qi) * HDIM;
        #pragma unroll
        for (int d4 = 0; d4 < HDIM; d4 += 4) {
            float4 v = *(const float4*)&src[d4];
            acc[d4]     += v.x;
            acc[d4 + 1] += v.y;
            acc[d4 + 2] += v.z;
            acc[d4 + 3] += v.w;
        }
    }
    #pragma unroll
    for (int d = 0; d < HDIM; d++)
        outp[(head * HDIM + d) * N_TOK + qi] = __float2half_rn(acc[d] * inv);
}

// ---------------- launcher ----------------------------------------------------
extern "C" void kernel_launch(void* const* d_in, const int* in_sizes, int n_in,
                              void* d_out, int out_size) {
    const float* x      = (const float*)d_in[0];
    const float* gamma  = (const float*)d_in[1];
    const float* beta   = (const float*)d_in[2];
    const float* qkv_w  = (const float*)d_in[3];
    const float* qkv_b  = (const float*)d_in[4];
    const float* proj_w = (const float*)d_in[5];
    const float* proj_b = (const float*)d_in[6];
    float* out = (float*)d_out;

    float *p_part, *p_scale, *p_shift, *p_po, *p_pl;
    __half *p_wqh, *p_wph, *p_hh, *p_qh, *p_kh, *p_vh, *p_attn;
    cudaGetSymbolAddress((void**)&p_part,  g_part);
    cudaGetSymbolAddress((void**)&p_scale, g_scale);
    cudaGetSymbolAddress((void**)&p_shift, g_shift);
    cudaGetSymbolAddress((void**)&p_wqh,   g_wqh);
    cudaGetSymbolAddress((void**)&p_wph,   g_wph);
    cudaGetSymbolAddress((void**)&p_hh,    g_hh);
    cudaGetSymbolAddress((void**)&p_qh,    g_qh);
    cudaGetSymbolAddress((void**)&p_kh,    g_kh);
    cudaGetSymbolAddress((void**)&p_vh,    g_vh);
    cudaGetSymbolAddress((void**)&p_attn,  g_attn);
    cudaGetSymbolAddress((void**)&p_po,    g_po);
    cudaGetSymbolAddress((void**)&p_pl,    g_pl);

    // 1/sqrt(32) * log2(e): scores come out in log2 domain
    const float qscale = 0.17677669529663687f * 1.44269504088896340f;

    // 1. GroupNorm stats + per-channel scale/shift; weight conversion
    gn_stats_kernel<<<GROUPS * GN_SL, 256>>>(x, p_part);
    conv_w_kernel<<<256, 256>>>(qkv_w, proj_w, p_wqh, p_wph);
    gn_final_kernel<<<1, 256>>>(p_part, gamma, beta, p_scale, p_shift);
    gn_half_kernel<<<1024, 256>>>(x, p_scale, p_shift, p_hh);

    // 2. QKV GEMM (fp16 cp.async pipeline, fp16 outputs)
    gemm16_kernel<<<dim3(N_TOK / 64, (3 * C_DIM) / 64), 128>>>(
        p_wqh, p_hh, qkv_b, nullptr, nullptr,
        p_qh, p_kh, p_vh, qscale, 0);

    // 3. Attention: fp16 flash kernel (cp.async double-buffered), split-KV x4
    attn_kernel<<<dim3(N_TOK / 64, HEADS, SPLIT), 128>>>(
        p_qh, p_kh, p_vh, p_po, p_pl);
    attn_combine_kernel<<<(N_TOK * HEADS) / 256, 256>>>(p_po, p_pl, p_attn);

    // 4. Proj GEMM (fp16 cp.async pipeline) + bias + residual -> d_out
    gemm16_kernel<<<dim3(N_TOK / 64, C_DIM / 64), 128>>>(
        p_wph, p_attn, proj_b, x, out,
        nullptr, nullptr, nullptr, 1.0f, 1);
}